// round 7
// baseline (speedup 1.0000x reference)
#include <cuda_runtime.h>
#include <cuda_bf16.h>
#include <stdint.h>

#define NCELL 81
#define TPB   512

// byte strides for bf16 tiles (16B-aligned rows)
#define ASTRB   272   // H1 / W2t tiles: 136 halves per row
#define YSTRB   208   // Yt / adj tiles: 104 halves per row

// ---- float-index smem layout ----
#define AHI_F   0        // H1_hi   96 x 136 halves (6528 f)
#define ALO_F   6528
#define BTHI_F  13056    // W2t_hi 128 x 136 halves (8704 f)
#define BTLO_F  21760
#define YTHI_F  30464    // Yt_hi  128 x 104 halves (6656 f)
#define YTLO_F  37120
#define ADJ_F   43776    // adj     96 x 104 halves (4992 f)
#define SW1_F   48768    // W1 10x128
#define SX_F    50048    // x 81x10 (+pad)
#define SZ_F    50864    // A_hat@x 81x10
#define SP_F    51680    // pooled 128
#define SB_F    51808    // b1|b2 256
#define TRIP_F  52064    // 540
#define SUM_F   52604    // 272
#define SM_FLOATS 52876  // 211504 B

// ================= constexpr index tables ===================================
struct U54 { unsigned v[54]; };
struct U27 { unsigned v[27]; };
struct U81 { unsigned v[81]; };

static constexpr U54 mkA() {
    U54 r{};
    for (int t = 0; t < 54; t++) {
        int c0 = 0, c1 = 0, c2 = 0;
        if (t < 27) { int i = t / 3, bj = t % 3, base = i * 9 + bj * 3;
                      c0 = base; c1 = base + 1; c2 = base + 2; }
        else        { int u = t - 27, j = u / 3, bi = u % 3, base = bi * 27 + j;
                      c0 = base; c1 = base + 9; c2 = base + 18; }
        r.v[t] = (unsigned)(c0 | (c1 << 8) | (c2 << 16));
    }
    return r;
}
static constexpr U27 mkB() {
    U27 r{};
    for (int s = 0; s < 27; s++) {
        int t0 = 0, t1 = 0, t2 = 0;
        if (s < 9)       { t0 = 3 * s; t1 = t0 + 1; t2 = t0 + 2; }
        else if (s < 18) { int j = s - 9; t0 = 27 + 3 * j; t1 = t0 + 1; t2 = t0 + 2; }
        else             { int bb = s - 18, bi = bb / 3, bj = bb % 3;
                           t0 = (3 * bi + 0) * 3 + bj; t1 = (3 * bi + 1) * 3 + bj;
                           t2 = (3 * bi + 2) * 3 + bj; }
        r.v[s] = (unsigned)(t0 | (t1 << 8) | (t2 << 16));
    }
    return r;
}
static constexpr U81 mkC() {
    U81 r{};
    for (int cell = 0; cell < 81; cell++) {
        int i = cell / 9, j = cell % 9, bi = i / 3, bj = j / 3;
        int b  = bi * 3 + bj;
        int ti = i * 3 + bj;
        int tj = j * 3 + bi;
        r.v[cell] = (unsigned)(i | (j << 4) | (b << 8) | (ti << 12) | (tj << 20));
    }
    return r;
}
__constant__ U54 cTabA = mkA();
__constant__ U27 cTabB = mkB();
__constant__ U81 cTabC = mkC();

// ================= PTX helpers ==============================================
__device__ __forceinline__ uint32_t smem_to_u32(const void* p) {
    uint32_t a;
    asm("{ .reg .u64 t; cvta.to.shared.u64 t, %1; cvt.u32.u64 %0, t; }"
        : "=r"(a) : "l"(p));
    return a;
}
__device__ __forceinline__ uint32_t cvt2bf16(float v0, float v1) {
    uint32_t r;
    asm("cvt.rn.bf16x2.f32 %0, %1, %2;" : "=r"(r) : "f"(v1), "f"(v0));
    return r;
}
__device__ __forceinline__ void ldsm4(uint32_t& r0, uint32_t& r1,
                                      uint32_t& r2, uint32_t& r3, uint32_t addr) {
    asm volatile("ldmatrix.sync.aligned.m8n8.x4.shared.b16 {%0,%1,%2,%3}, [%4];"
                 : "=r"(r0), "=r"(r1), "=r"(r2), "=r"(r3) : "r"(addr));
}
__device__ __forceinline__ void ldsm2(uint32_t& r0, uint32_t& r1, uint32_t addr) {
    asm volatile("ldmatrix.sync.aligned.m8n8.x2.shared.b16 {%0,%1}, [%2];"
                 : "=r"(r0), "=r"(r1) : "r"(addr));
}
__device__ __forceinline__ void mma16816(float* c, uint32_t a0, uint32_t a1,
                                         uint32_t a2, uint32_t a3,
                                         uint32_t b0, uint32_t b1) {
    asm volatile(
        "mma.sync.aligned.m16n8k16.row.col.f32.bf16.bf16.f32 "
        "{%0,%1,%2,%3}, {%4,%5,%6,%7}, {%8,%9}, {%0,%1,%2,%3};"
        : "+f"(c[0]), "+f"(c[1]), "+f"(c[2]), "+f"(c[3])
        : "r"(a0), "r"(a1), "r"(a2), "r"(a3), "r"(b0), "r"(b1));
}

// ================= main kernel ==============================================
__global__ __launch_bounds__(TPB, 1)
void sudoku_gnn_kernel(const float* __restrict__ x,
                       const float* __restrict__ W1, const float* __restrict__ b1,
                       const float* __restrict__ W2, const float* __restrict__ b2,
                       const float* __restrict__ Wa, const float* __restrict__ ba,
                       const float* __restrict__ Wc, const float* __restrict__ bc,
                       const float* __restrict__ Wn, const float* __restrict__ bn,
                       const float* __restrict__ Wt, const float* __restrict__ bt,
                       float* __restrict__ out)
{
    extern __shared__ float sm[];
    char*  smb = (char*)sm;
    float* sW1 = sm + SW1_F;
    float* sX  = sm + SX_F;
    float* sZ  = sm + SZ_F;
    float* sP  = sm + SP_F;
    float* sB  = sm + SB_F;
    float* sTripF = sm + TRIP_F;
    float* sSumF  = sm + SUM_F;

    const int tid  = threadIdx.x;
    const int wid  = tid >> 5;
    const int lane = tid & 31;
    const int g    = blockIdx.x;
    const uint32_t smu = smem_to_u32(sm);

    // ---- stage: W2 -> W2t_hi/lo bf16 (n-major k-contiguous) ----
    for (int it = tid; it < 2048; it += TPB) {
        int kq = it >> 7, n = it & 127;
        int k0 = kq << 3;
        uint32_t hi[4], lo[4];
        #pragma unroll
        for (int p = 0; p < 4; p++) {
            float w0 = W2[(k0 + 2 * p) * 128 + n];
            float w1 = W2[(k0 + 2 * p + 1) * 128 + n];
            uint32_t h = cvt2bf16(w0, w1);
            float f0 = __uint_as_float(h << 16);
            float f1 = __uint_as_float(h & 0xFFFF0000u);
            hi[p] = h;
            lo[p] = cvt2bf16(w0 - f0, w1 - f1);
        }
        uint32_t off = (uint32_t)n * ASTRB + (uint32_t)k0 * 2;
        *(uint4*)(smb + BTHI_F * 4 + off) = make_uint4(hi[0], hi[1], hi[2], hi[3]);
        *(uint4*)(smb + BTLO_F * 4 + off) = make_uint4(lo[0], lo[1], lo[2], lo[3]);
    }
    // ---- build adjacency+I (0/1 bf16, rows 96 x 96 cols, packed pairs) ----
    for (int it = tid; it < 96 * 48; it += TPB) {
        int i = it / 48, mp = it - (it / 48) * 48;
        int m0 = mp << 1, m1 = m0 + 1;
        uint32_t v = 0;
        if (i < NCELL) {
            int ri = i / 9, ci = i - ri * 9;
            if (m0 < NCELL) {
                int rm = m0 / 9, cm = m0 - rm * 9;
                bool adj = (ri == rm) || (ci == cm) ||
                           ((ri / 3 == rm / 3) && (ci / 3 == cm / 3));
                if (adj) v |= 0x3F80u;
            }
            if (m1 < NCELL) {
                int rm = m1 / 9, cm = m1 - rm * 9;
                bool adj = (ri == rm) || (ci == cm) ||
                           ((ri / 3 == rm / 3) && (ci / 3 == cm / 3));
                if (adj) v |= 0x3F800000u;
            }
        }
        *(uint32_t*)(smb + ADJ_F * 4 + (uint32_t)i * YSTRB + (uint32_t)m0 * 2) = v;
    }
    if (tid < 320) ((float4*)sW1)[tid] = ((const float4*)W1)[tid];
    {
        const float* xg = x + (size_t)g * (NCELL * 10);
        for (int i = tid; i < NCELL * 10; i += TPB) sX[i] = xg[i];
    }
    if (tid < 128) { sB[tid] = b1[tid]; sB[128 + tid] = b2[tid]; }
    __syncthreads();

    // ---- Phase 1: Zx = (A_hat @ X) on 10 raw channels ----
    for (int it = tid; it < 54 * 10; it += TPB) {
        int t = it / 10, f = it - t * 10;
        unsigned pk = cTabA.v[t];
        sTripF[it] = sX[(pk & 255) * 10 + f] + sX[((pk >> 8) & 255) * 10 + f]
                   + sX[((pk >> 16) & 255) * 10 + f];
    }
    __syncthreads();
    for (int it = tid; it < 27 * 10; it += TPB) {
        int s = it / 10, f = it - s * 10;
        unsigned pk = cTabB.v[s];
        sSumF[it] = sTripF[(pk & 255) * 10 + f] + sTripF[((pk >> 8) & 255) * 10 + f]
                  + sTripF[((pk >> 16) & 255) * 10 + f];
    }
    __syncthreads();
    for (int it = tid; it < NCELL * 10; it += TPB) {
        int cell = it / 10, f = it - cell * 10;
        unsigned pk = cTabC.v[cell];
        int i  = pk & 15, j = (pk >> 4) & 15, b = (pk >> 8) & 15;
        int ti = (pk >> 12) & 31, tj = (pk >> 20) & 31;
        float agg = sSumF[i * 10 + f] + sSumF[(9 + j) * 10 + f]
                  + sSumF[(18 + b) * 10 + f]
                  - sTripF[ti * 10 + f] - sTripF[(27 + tj) * 10 + f];
        sZ[it] = agg * (1.0f / 21.0f);
    }
    __syncthreads();

    // ---- Phase 2: H1 = relu(Zx@W1 + b1) -> bf16 hi/lo A tiles ----
    for (int it = tid; it < NCELL * 8; it += TPB) {
        int cell = it >> 3, oct = it & 7;
        int kb = oct << 4;
        float z[10];
        #pragma unroll
        for (int f = 0; f < 10; f++) z[f] = sZ[cell * 10 + f];
        uint32_t rowOff = (uint32_t)cell * ASTRB;
        #pragma unroll
        for (int kp = 0; kp < 8; kp++) {
            int k = kb + (kp << 1);
            float v0 = sB[k], v1 = sB[k + 1];
            #pragma unroll
            for (int f = 0; f < 10; f++) {
                float2 wv = *(const float2*)(sW1 + f * 128 + k);
                v0 = fmaf(z[f], wv.x, v0);
                v1 = fmaf(z[f], wv.y, v1);
            }
            v0 = v0 > 0.0f ? v0 : 0.0f;
            v1 = v1 > 0.0f ? v1 : 0.0f;
            uint32_t h = cvt2bf16(v0, v1);
            float f0 = __uint_as_float(h << 16);
            float f1 = __uint_as_float(h & 0xFFFF0000u);
            uint32_t l = cvt2bf16(v0 - f0, v1 - f1);
            uint32_t off = rowOff + (uint32_t)k * 2;
            *(uint32_t*)(smb + AHI_F * 4 + off) = h;
            *(uint32_t*)(smb + ALO_F * 4 + off) = l;
        }
    }
    // zero pad rows 81..95
    for (int it = tid; it < 15 * 64; it += TPB) {
        int cell = NCELL + (it >> 6), kp = it & 63;
        uint32_t off = (uint32_t)cell * ASTRB + (uint32_t)kp * 4;
        *(uint32_t*)(smb + AHI_F * 4 + off) = 0u;
        *(uint32_t*)(smb + ALO_F * 4 + off) = 0u;
    }
    __syncthreads();

    // ---- Phase 3: Y2^T = W2^T @ H1^T via mma (A=W2t, B=H1), 3-term ----
    {
        const int mtc   = wid >> 1;              // channel tile 0..7 (16 ch)
        const int ntgrp = (wid & 1) * 6;         // cell ntile base (6 tiles = 48 cells)
        const int arow  = lane & 15;
        const int akoff = (lane & 16) ? 8 : 0;
        const int brow  = lane & 7;
        const int bkoff = (lane & 8) ? 8 : 0;

        float acc[6][4];
        #pragma unroll
        for (int nt = 0; nt < 6; nt++)
            #pragma unroll
            for (int q = 0; q < 4; q++) acc[nt][q] = 0.0f;

        const uint32_t aHi = smu + BTHI_F * 4;   // A operand = W2t
        const uint32_t aLo = smu + BTLO_F * 4;
        const uint32_t bHi = smu + AHI_F * 4;    // B operand = H1
        const uint32_t bLo = smu + ALO_F * 4;

        #pragma unroll
        for (int ks = 0; ks < 8; ks++) {
            const int k0 = ks << 4;
            uint32_t aOff = (uint32_t)(mtc * 16 + arow) * ASTRB
                          + (uint32_t)(k0 + akoff) * 2;
            uint32_t ah0, ah1, ah2, ah3, al0, al1, al2, al3;
            ldsm4(ah0, ah1, ah2, ah3, aHi + aOff);
            ldsm4(al0, al1, al2, al3, aLo + aOff);
            #pragma unroll
            for (int nt = 0; nt < 6; nt++) {
                uint32_t bOff = (uint32_t)((ntgrp + nt) * 8 + brow) * ASTRB
                              + (uint32_t)(k0 + bkoff) * 2;
                uint32_t bh0, bh1, bl0, bl1;
                ldsm2(bh0, bh1, bHi + bOff);
                ldsm2(bl0, bl1, bLo + bOff);
                mma16816(acc[nt], ah0, ah1, ah2, ah3, bh0, bh1);
                mma16816(acc[nt], ah0, ah1, ah2, ah3, bl0, bl1);
                mma16816(acc[nt], al0, al1, al2, al3, bh0, bh1);
            }
        }
        // epilogue: write Yt (channel-major, cells contiguous) packed bf16x2
        const int chr0 = mtc * 16 + (lane >> 2);
        #pragma unroll
        for (int nt = 0; nt < 6; nt++) {
            int c = (ntgrp + nt) * 8 + ((lane & 3) << 1);
            // row chr0: cells c, c+1
            uint32_t h0 = cvt2bf16(acc[nt][0], acc[nt][1]);
            float r0 = acc[nt][0] - __uint_as_float(h0 << 16);
            float r1 = acc[nt][1] - __uint_as_float(h0 & 0xFFFF0000u);
            uint32_t l0 = cvt2bf16(r0, r1);
            // row chr0+8: cells c, c+1
            uint32_t h1 = cvt2bf16(acc[nt][2], acc[nt][3]);
            float r2 = acc[nt][2] - __uint_as_float(h1 << 16);
            float r3 = acc[nt][3] - __uint_as_float(h1 & 0xFFFF0000u);
            uint32_t l1 = cvt2bf16(r2, r3);
            uint32_t off0 = (uint32_t)chr0 * YSTRB + (uint32_t)c * 2;
            uint32_t off1 = off0 + 8u * YSTRB;
            *(uint32_t*)(smb + YTHI_F * 4 + off0) = h0;
            *(uint32_t*)(smb + YTLO_F * 4 + off0) = l0;
            *(uint32_t*)(smb + YTHI_F * 4 + off1) = h1;
            *(uint32_t*)(smb + YTLO_F * 4 + off1) = l1;
        }
    }
    __syncthreads();

    // ---- Phase 4: agg = Adj @ Y2 via mma (A=adj, B=Yt), 2-term; fused
    //      bias+relu+mean-pool epilogue in registers ----
    {
        const int n0    = wid << 3;              // warp owns 8 channels
        const int arow  = lane & 15;
        const int akoff = (lane & 16) ? 8 : 0;
        const int brow  = lane & 7;
        const int bkoff = (lane & 8) ? 8 : 0;

        float acc[6][4];
        #pragma unroll
        for (int mt = 0; mt < 6; mt++)
            #pragma unroll
            for (int q = 0; q < 4; q++) acc[mt][q] = 0.0f;

        const uint32_t adjB = smu + ADJ_F * 4;
        const uint32_t yHi  = smu + YTHI_F * 4;
        const uint32_t yLo  = smu + YTLO_F * 4;

        #pragma unroll
        for (int ks = 0; ks < 6; ks++) {
            const int k0 = ks << 4;
            uint32_t bOff = (uint32_t)(n0 + brow) * YSTRB
                          + (uint32_t)(k0 + bkoff) * 2;
            uint32_t bh0, bh1, bl0, bl1;
            ldsm2(bh0, bh1, yHi + bOff);
            ldsm2(bl0, bl1, yLo + bOff);
            #pragma unroll
            for (int mt = 0; mt < 6; mt++) {
                uint32_t aOff = (uint32_t)(mt * 16 + arow) * YSTRB
                              + (uint32_t)(k0 + akoff) * 2;
                uint32_t a0, a1, a2, a3;
                ldsm4(a0, a1, a2, a3, adjB + aOff);
                mma16816(acc[mt], a0, a1, a2, a3, bh0, bh1);
                mma16816(acc[mt], a0, a1, a2, a3, bl0, bl1);
            }
        }

        // fused epilogue: v = relu(acc/21 + b2), pool over cells < 81
        const int cA = n0 + ((lane & 3) << 1);
        const float bA = sB[128 + cA];
        const float bB = sB[128 + cA + 1];
        const int rb = lane >> 2;
        float pA = 0.0f, pB = 0.0f;
        #pragma unroll
        for (int mt = 0; mt < 6; mt++) {
            float v0 = fmaf(acc[mt][0], (1.0f / 21.0f), bA); v0 = v0 > 0.f ? v0 : 0.f;
            float v1 = fmaf(acc[mt][1], (1.0f / 21.0f), bB); v1 = v1 > 0.f ? v1 : 0.f;
            float v2 = fmaf(acc[mt][2], (1.0f / 21.0f), bA); v2 = v2 > 0.f ? v2 : 0.f;
            float v3 = fmaf(acc[mt][3], (1.0f / 21.0f), bB); v3 = v3 > 0.f ? v3 : 0.f;
            if (mt < 5) {                       // rows mt*16+rb and +8 all < 81
                pA += v0 + v2; pB += v1 + v3;
            } else if (rb == 0) {               // row 80 only
                pA += v0; pB += v1;
            }
        }
        #pragma unroll
        for (int s = 4; s < 32; s <<= 1) {
            pA += __shfl_xor_sync(0xFFFFFFFFu, pA, s);
            pB += __shfl_xor_sync(0xFFFFFFFFu, pB, s);
        }
        if (lane < 4) {
            sP[cA]     = pA * (1.0f / 81.0f);
            sP[cA + 1] = pB * (1.0f / 81.0f);
        }
    }
    __syncthreads();

    // ---- Phase 5: heads ----
    if (tid < 104) {
        const float* W; const float* bb; int nc, col; size_t off;
        if (tid < 4)       { W = Wa; bb = ba; nc = 4;  col = tid;      off = (size_t)g * 4 + col; }
        else if (tid < 85) { W = Wc; bb = bc; nc = 81; col = tid - 4;  off = 8192u   + (size_t)g * 81 + col; }
        else if (tid < 94) { W = Wn; bb = bn; nc = 9;  col = tid - 85; off = 174080u + (size_t)g * 9  + col; }
        else               { W = Wt; bb = bt; nc = 10; col = tid - 94; off = 192512u + (size_t)g * 10 + col; }
        float acc = bb[col];
        #pragma unroll 8
        for (int k = 0; k < 128; k++)
            acc = fmaf(sP[k], W[k * nc + col], acc);
        out[off] = acc;
    }
}

extern "C" void kernel_launch(void* const* d_in, const int* in_sizes, int n_in,
                              void* d_out, int out_size)
{
    const float* x  = (const float*)d_in[0];
    const float* W1 = (const float*)d_in[3];
    const float* b1 = (const float*)d_in[4];
    const float* W2 = (const float*)d_in[5];
    const float* b2 = (const float*)d_in[6];
    const float* Wa = (const float*)d_in[7];
    const float* ba = (const float*)d_in[8];
    const float* Wc = (const float*)d_in[9];
    const float* bc = (const float*)d_in[10];
    const float* Wn = (const float*)d_in[11];
    const float* bn = (const float*)d_in[12];
    const float* Wt = (const float*)d_in[13];
    const float* bt = (const float*)d_in[14];
    float* out = (float*)d_out;

    const int nGraphs = in_sizes[0] / (NCELL * 10);   // 2048
    const size_t smemBytes = (size_t)SM_FLOATS * sizeof(float);  // ~211.5 KB

    cudaFuncSetAttribute(sudoku_gnn_kernel,
                         cudaFuncAttributeMaxDynamicSharedMemorySize,
                         (int)smemBytes);

    sudoku_gnn_kernel<<<nGraphs, TPB, smemBytes>>>(
        x, W1, b1, W2, b2, Wa, ba, Wc, bc, Wn, bn, Wt, bt, out);
}

// round 8
// speedup vs baseline: 1.5212x; 1.5212x over previous
#include <cuda_runtime.h>
#include <cuda_bf16.h>
#include <stdint.h>

#define NCELL 81
#define TPB   512

// bf16 tiles use row stride 136 halves (272 B): 16B-aligned, ldmatrix conflict-free
#define ASTR  136
// ---- float-index smem layout (46240 floats = 184960 B) ----
#define AHI_F 0        // A_hi 96 x 136 bf16  (6528 floats)
#define ALO_F 6528
#define BHI_F 13056    // Bt_hi 128 x 136 bf16 (8704 floats)
#define BLO_F 21760
#define SH_F  30464    // Y2/H2 fp32 96 x 130 (12480)
#define SH_STR 130
#define SW1_F 42944    // W1 10x128
#define SX_F  44224    // x 81x10
#define SZ_F  45040    // A_hat@x 81x10
#define SP_F  45856    // pooled 128
#define SB_F  45984    // b1|b2 256
#define SM_FLOATS 46240
// agg scratch overlaps (temporally dead) A region
#define TRIP_F 0
#define SUM_F  6912

// ================= constexpr index tables ===================================
struct U54 { unsigned v[54]; };
struct U27 { unsigned v[27]; };
struct U81 { unsigned v[81]; };

static constexpr U54 mkA() {
    U54 r{};
    for (int t = 0; t < 54; t++) {
        int c0 = 0, c1 = 0, c2 = 0;
        if (t < 27) { int i = t / 3, bj = t % 3, base = i * 9 + bj * 3;
                      c0 = base; c1 = base + 1; c2 = base + 2; }
        else        { int u = t - 27, j = u / 3, bi = u % 3, base = bi * 27 + j;
                      c0 = base; c1 = base + 9; c2 = base + 18; }
        r.v[t] = (unsigned)(c0 | (c1 << 8) | (c2 << 16));
    }
    return r;
}
static constexpr U27 mkB() {
    U27 r{};
    for (int s = 0; s < 27; s++) {
        int t0 = 0, t1 = 0, t2 = 0;
        if (s < 9)       { t0 = 3 * s; t1 = t0 + 1; t2 = t0 + 2; }
        else if (s < 18) { int j = s - 9; t0 = 27 + 3 * j; t1 = t0 + 1; t2 = t0 + 2; }
        else             { int bb = s - 18, bi = bb / 3, bj = bb % 3;
                           t0 = (3 * bi + 0) * 3 + bj; t1 = (3 * bi + 1) * 3 + bj;
                           t2 = (3 * bi + 2) * 3 + bj; }
        r.v[s] = (unsigned)(t0 | (t1 << 8) | (t2 << 16));
    }
    return r;
}
static constexpr U81 mkC() {
    U81 r{};
    for (int cell = 0; cell < 81; cell++) {
        int i = cell / 9, j = cell % 9, bi = i / 3, bj = j / 3;
        int b  = bi * 3 + bj;
        int ti = i * 3 + bj;
        int tj = j * 3 + bi;
        r.v[cell] = (unsigned)(i | (j << 4) | (b << 8) | (ti << 12) | (tj << 20));
    }
    return r;
}
__constant__ U54 cTabA = mkA();
__constant__ U27 cTabB = mkB();
__constant__ U81 cTabC = mkC();

// ================= PTX helpers ==============================================
__device__ __forceinline__ uint32_t smem_to_u32(const void* p) {
    uint32_t a;
    asm("{ .reg .u64 t; cvta.to.shared.u64 t, %1; cvt.u32.u64 %0, t; }"
        : "=r"(a) : "l"(p));
    return a;
}
// pack two floats to bf16x2 (v0 -> low half, v1 -> high half)
__device__ __forceinline__ uint32_t cvt2bf16(float v0, float v1) {
    uint32_t r;
    asm("cvt.rn.bf16x2.f32 %0, %1, %2;" : "=r"(r) : "f"(v1), "f"(v0));
    return r;
}
__device__ __forceinline__ void ldsm4(uint32_t& r0, uint32_t& r1,
                                      uint32_t& r2, uint32_t& r3, uint32_t addr) {
    asm volatile("ldmatrix.sync.aligned.m8n8.x4.shared.b16 {%0,%1,%2,%3}, [%4];"
                 : "=r"(r0), "=r"(r1), "=r"(r2), "=r"(r3) : "r"(addr));
}
__device__ __forceinline__ void ldsm2(uint32_t& r0, uint32_t& r1, uint32_t addr) {
    asm volatile("ldmatrix.sync.aligned.m8n8.x2.shared.b16 {%0,%1}, [%2];"
                 : "=r"(r0), "=r"(r1) : "r"(addr));
}
__device__ __forceinline__ void mma16816(float* c, uint32_t a0, uint32_t a1,
                                         uint32_t a2, uint32_t a3,
                                         uint32_t b0, uint32_t b1) {
    asm volatile(
        "mma.sync.aligned.m16n8k16.row.col.f32.bf16.bf16.f32 "
        "{%0,%1,%2,%3}, {%4,%5,%6,%7}, {%8,%9}, {%0,%1,%2,%3};"
        : "+f"(c[0]), "+f"(c[1]), "+f"(c[2]), "+f"(c[3])
        : "r"(a0), "r"(a1), "r"(a2), "r"(a3), "r"(b0), "r"(b1));
}

// ========== full 128-ch aggregation + bias + relu on 96x130 buffer ==========
__device__ __forceinline__ void agg_relu130(float* __restrict__ buf,
                                            const float* __restrict__ biasSm,
                                            float* __restrict__ sTripF,
                                            float* __restrict__ sSumF,
                                            int tid)
{
    float2* T2 = (float2*)sTripF;
    float2* S2 = (float2*)sSumF;
    const float2* B2 = (const float2*)biasSm;

    __syncthreads();

    for (int it = tid; it < 54 * 64; it += TPB) {
        int t = it >> 6, cp = it & 63;
        unsigned pk = cTabA.v[t];
        float2 a = ((const float2*)(buf + (pk & 255)         * SH_STR))[cp];
        float2 b = ((const float2*)(buf + ((pk >> 8) & 255)  * SH_STR))[cp];
        float2 c = ((const float2*)(buf + ((pk >> 16) & 255) * SH_STR))[cp];
        T2[it] = make_float2(a.x + b.x + c.x, a.y + b.y + c.y);
    }
    __syncthreads();

    for (int it = tid; it < 27 * 64; it += TPB) {
        int s = it >> 6, cp = it & 63;
        unsigned pk = cTabB.v[s];
        float2 a = T2[(pk & 255) * 64 + cp];
        float2 b = T2[((pk >> 8) & 255) * 64 + cp];
        float2 c = T2[((pk >> 16) & 255) * 64 + cp];
        S2[it] = make_float2(a.x + b.x + c.x, a.y + b.y + c.y);
    }
    __syncthreads();

    for (int it = tid; it < NCELL * 64; it += TPB) {
        int cell = it >> 6, cp = it & 63;
        unsigned pk = cTabC.v[cell];
        int i  = pk & 15, j = (pk >> 4) & 15, b = (pk >> 8) & 15;
        int ti = (pk >> 12) & 31, tj = (pk >> 20) & 31;
        float2 sR  = S2[i * 64 + cp];
        float2 sC  = S2[(9 + j) * 64 + cp];
        float2 sBx = S2[(18 + b) * 64 + cp];
        float2 tR  = T2[ti * 64 + cp];
        float2 tC  = T2[(27 + tj) * 64 + cp];
        float2 bia = B2[cp];
        float vx = (sR.x + sC.x + sBx.x - tR.x - tC.x) * (1.0f / 21.0f) + bia.x;
        float vy = (sR.y + sC.y + sBx.y - tR.y - tC.y) * (1.0f / 21.0f) + bia.y;
        ((float2*)(buf + cell * SH_STR))[cp] =
            make_float2(vx > 0.0f ? vx : 0.0f, vy > 0.0f ? vy : 0.0f);
    }
    __syncthreads();
}

// ================= main kernel ==============================================
__global__ __launch_bounds__(TPB, 1)
void sudoku_gnn_kernel(const float* __restrict__ x,
                       const float* __restrict__ W1, const float* __restrict__ b1,
                       const float* __restrict__ W2, const float* __restrict__ b2,
                       const float* __restrict__ Wa, const float* __restrict__ ba,
                       const float* __restrict__ Wc, const float* __restrict__ bc,
                       const float* __restrict__ Wn, const float* __restrict__ bn,
                       const float* __restrict__ Wt, const float* __restrict__ bt,
                       float* __restrict__ out)
{
    extern __shared__ float sm[];
    char*  smb = (char*)sm;
    float* sH  = sm + SH_F;
    float* sW1 = sm + SW1_F;
    float* sX  = sm + SX_F;
    float* sZ  = sm + SZ_F;
    float* sP  = sm + SP_F;
    float* sB  = sm + SB_F;
    float* sTripF = sm + TRIP_F;
    float* sSumF  = sm + SUM_F;

    const int tid  = threadIdx.x;
    const int wid  = tid >> 5;
    const int lane = tid & 31;
    const int g    = blockIdx.x;
    const uint32_t smu = smem_to_u32(sm);

    // ---- stage: W2 -> Bt_hi/Bt_lo bf16 (n-major, transpose on the fly) ----
    for (int it = tid; it < 2048; it += TPB) {
        int kq = it >> 7, n = it & 127;
        int k0 = kq << 3;
        uint32_t hi[4], lo[4];
        #pragma unroll
        for (int p = 0; p < 4; p++) {
            float w0 = W2[(k0 + 2 * p) * 128 + n];
            float w1 = W2[(k0 + 2 * p + 1) * 128 + n];
            uint32_t h = cvt2bf16(w0, w1);
            float f0 = __uint_as_float(h << 16);
            float f1 = __uint_as_float(h & 0xFFFF0000u);
            hi[p] = h;
            lo[p] = cvt2bf16(w0 - f0, w1 - f1);
        }
        uint32_t off = (uint32_t)n * (ASTR * 2) + (uint32_t)k0 * 2;  // 16B aligned
        *(uint4*)(smb + BHI_F * 4 + off) = make_uint4(hi[0], hi[1], hi[2], hi[3]);
        *(uint4*)(smb + BLO_F * 4 + off) = make_uint4(lo[0], lo[1], lo[2], lo[3]);
    }
    if (tid < 320) ((float4*)sW1)[tid] = ((const float4*)W1)[tid];
    {
        const float* xg = x + (size_t)g * (NCELL * 10);
        for (int i = tid; i < NCELL * 10; i += TPB) sX[i] = xg[i];
    }
    if (tid < 128) { sB[tid] = b1[tid]; sB[128 + tid] = b2[tid]; }
    __syncthreads();

    // ---- Phase 1: Zx = (A_hat @ X) on 10 raw channels (scratch in A region)
    for (int it = tid; it < 54 * 10; it += TPB) {
        int t = it / 10, f = it - t * 10;
        unsigned pk = cTabA.v[t];
        sTripF[it] = sX[(pk & 255) * 10 + f] + sX[((pk >> 8) & 255) * 10 + f]
                   + sX[((pk >> 16) & 255) * 10 + f];
    }
    __syncthreads();
    for (int it = tid; it < 27 * 10; it += TPB) {
        int s = it / 10, f = it - s * 10;
        unsigned pk = cTabB.v[s];
        sSumF[it] = sTripF[(pk & 255) * 10 + f] + sTripF[((pk >> 8) & 255) * 10 + f]
                  + sTripF[((pk >> 16) & 255) * 10 + f];
    }
    __syncthreads();
    for (int it = tid; it < NCELL * 10; it += TPB) {
        int cell = it / 10, f = it - cell * 10;
        unsigned pk = cTabC.v[cell];
        int i  = pk & 15, j = (pk >> 4) & 15, b = (pk >> 8) & 15;
        int ti = (pk >> 12) & 31, tj = (pk >> 20) & 31;
        float agg = sSumF[i * 10 + f] + sSumF[(9 + j) * 10 + f]
                  + sSumF[(18 + b) * 10 + f]
                  - sTripF[ti * 10 + f] - sTripF[(27 + tj) * 10 + f];
        sZ[it] = agg * (1.0f / 21.0f);
    }
    __syncthreads();

    // ---- Phase 2: H1 = relu(Zx@W1 + b1) -> bf16 hi/lo straight into A tiles
    // also zero pad rows 81..95 so ldmatrix reads clean data
    for (int it = tid; it < 96 * 64; it += TPB) {
        int cell = it >> 6, kp = it & 63;
        int k = kp << 1;
        uint32_t h = 0u, l = 0u;
        if (cell < NCELL) {
            const float* z = sZ + cell * 10;
            float v0 = sB[k], v1 = sB[k + 1];
            #pragma unroll
            for (int f = 0; f < 10; f++) {
                float zf = z[f];
                float2 wv = *(const float2*)(sW1 + f * 128 + k);
                v0 = fmaf(zf, wv.x, v0);
                v1 = fmaf(zf, wv.y, v1);
            }
            v0 = v0 > 0.0f ? v0 : 0.0f;
            v1 = v1 > 0.0f ? v1 : 0.0f;
            h = cvt2bf16(v0, v1);
            float f0 = __uint_as_float(h << 16);
            float f1 = __uint_as_float(h & 0xFFFF0000u);
            l = cvt2bf16(v0 - f0, v1 - f1);
        }
        uint32_t off = (uint32_t)cell * (ASTR * 2) + (uint32_t)k * 2;
        *(uint32_t*)(smb + AHI_F * 4 + off) = h;
        *(uint32_t*)(smb + ALO_F * 4 + off) = l;
    }
    __syncthreads();

    // ---- Phase 3: Y2 = H1 @ W2 via mma.sync bf16, 3-term compensated ----
    // 2-D warp tiling: warp = (2 n-tiles) x (3 m-tiles); halves A traffic vs
    // the 1x6 column-strip mapping.
    {
        const int nt0 = (wid >> 1) * 2;          // first of 2 n-tiles (8 ch each)
        const int mt0 = (wid & 1) * 3;           // first of 3 m-tiles (16 rows)
        const int arow = lane & 15;
        const int akoff = (lane & 16) ? 8 : 0;
        const int brow = lane & 7;
        const int bkoff = (lane & 8) ? 8 : 0;

        float acc[3][2][4];
        #pragma unroll
        for (int mt = 0; mt < 3; mt++)
            #pragma unroll
            for (int nt = 0; nt < 2; nt++)
                #pragma unroll
                for (int q = 0; q < 4; q++) acc[mt][nt][q] = 0.0f;

        const uint32_t aHi = smu + AHI_F * 4;
        const uint32_t aLo = smu + ALO_F * 4;
        const uint32_t bHi = smu + BHI_F * 4;
        const uint32_t bLo = smu + BLO_F * 4;

        #pragma unroll
        for (int ks = 0; ks < 8; ks++) {
            const int k0 = ks << 4;
            // B fragments: 2 n-tiles, hi+lo
            uint32_t bh[2][2], bl[2][2];
            #pragma unroll
            for (int nt = 0; nt < 2; nt++) {
                uint32_t bOff = (uint32_t)((nt0 + nt) * 8 + brow) * (ASTR * 2)
                              + (uint32_t)(k0 + bkoff) * 2;
                ldsm2(bh[nt][0], bh[nt][1], bHi + bOff);
                ldsm2(bl[nt][0], bl[nt][1], bLo + bOff);
            }
            // A fragments: 3 m-tiles, hi+lo; 3 MMA terms each
            #pragma unroll
            for (int mt = 0; mt < 3; mt++) {
                uint32_t aOff = (uint32_t)((mt0 + mt) * 16 + arow) * (ASTR * 2)
                              + (uint32_t)(k0 + akoff) * 2;
                uint32_t ah0, ah1, ah2, ah3, al0, al1, al2, al3;
                ldsm4(ah0, ah1, ah2, ah3, aHi + aOff);
                ldsm4(al0, al1, al2, al3, aLo + aOff);
                #pragma unroll
                for (int nt = 0; nt < 2; nt++) {
                    mma16816(acc[mt][nt], ah0, ah1, ah2, ah3, bh[nt][0], bh[nt][1]);
                    mma16816(acc[mt][nt], ah0, ah1, ah2, ah3, bl[nt][0], bl[nt][1]);
                    mma16816(acc[mt][nt], al0, al1, al2, al3, bh[nt][0], bh[nt][1]);
                }
            }
        }
        // epilogue: scatter D fragments into sH (stride 130)
        const int rbase = lane >> 2;
        #pragma unroll
        for (int mt = 0; mt < 3; mt++) {
            int row = (mt0 + mt) * 16 + rbase;
            #pragma unroll
            for (int nt = 0; nt < 2; nt++) {
                int col = (nt0 + nt) * 8 + ((lane & 3) << 1);
                *(float2*)(sH + row * SH_STR + col) =
                    make_float2(acc[mt][nt][0], acc[mt][nt][1]);
                *(float2*)(sH + (row + 8) * SH_STR + col) =
                    make_float2(acc[mt][nt][2], acc[mt][nt][3]);
            }
        }
    }

    // ---- Phase 4: H2 = relu(agg(Y2)/21 + b2) in place ----
    agg_relu130(sH, sB + 128, sTripF, sSumF, tid);

    // ---- Phase 5: mean pool (4-way split, scratch in A region) ----
    {
        int c = tid & 127, grp4 = tid >> 7;
        int cStart = grp4 * 21;
        int cEnd = cStart + 21; if (cEnd > NCELL) cEnd = NCELL;
        float acc = 0.0f;
        for (int cell = cStart; cell < cEnd; cell++) acc += sH[cell * SH_STR + c];
        sTripF[grp4 * 128 + c] = acc;
    }
    __syncthreads();
    if (tid < 128) {
        sP[tid] = (sTripF[tid] + sTripF[128 + tid] + sTripF[256 + tid]
                 + sTripF[384 + tid]) * (1.0f / 81.0f);
    }
    __syncthreads();

    // ---- Phase 6: heads ----
    if (tid < 104) {
        const float* W; const float* bb; int nc, col; size_t off;
        if (tid < 4)       { W = Wa; bb = ba; nc = 4;  col = tid;      off = (size_t)g * 4 + col; }
        else if (tid < 85) { W = Wc; bb = bc; nc = 81; col = tid - 4;  off = 8192u   + (size_t)g * 81 + col; }
        else if (tid < 94) { W = Wn; bb = bn; nc = 9;  col = tid - 85; off = 174080u + (size_t)g * 9  + col; }
        else               { W = Wt; bb = bt; nc = 10; col = tid - 94; off = 192512u + (size_t)g * 10 + col; }
        float acc = bb[col];
        #pragma unroll 8
        for (int k = 0; k < 128; k++)
            acc = fmaf(sP[k], W[k * nc + col], acc);
        out[off] = acc;
    }
}

extern "C" void kernel_launch(void* const* d_in, const int* in_sizes, int n_in,
                              void* d_out, int out_size)
{
    const float* x  = (const float*)d_in[0];
    const float* W1 = (const float*)d_in[3];
    const float* b1 = (const float*)d_in[4];
    const float* W2 = (const float*)d_in[5];
    const float* b2 = (const float*)d_in[6];
    const float* Wa = (const float*)d_in[7];
    const float* ba = (const float*)d_in[8];
    const float* Wc = (const float*)d_in[9];
    const float* bc = (const float*)d_in[10];
    const float* Wn = (const float*)d_in[11];
    const float* bn = (const float*)d_in[12];
    const float* Wt = (const float*)d_in[13];
    const float* bt = (const float*)d_in[14];
    float* out = (float*)d_out;

    const int nGraphs = in_sizes[0] / (NCELL * 10);   // 2048
    const size_t smemBytes = (size_t)SM_FLOATS * sizeof(float);  // ~181 KB

    cudaFuncSetAttribute(sudoku_gnn_kernel,
                         cudaFuncAttributeMaxDynamicSharedMemorySize,
                         (int)smemBytes);

    sudoku_gnn_kernel<<<nGraphs, TPB, smemBytes>>>(
        x, W1, b1, W2, b2, Wa, ba, Wc, bc, Wn, bn, Wt, bt, out);
}

// round 10
// speedup vs baseline: 1.9311x; 1.2695x over previous
#include <cuda_runtime.h>
#include <cuda_bf16.h>
#include <stdint.h>

#define NCELL 81
#define TPB   256

// bf16 A tiles: row stride 136 halves (272 B), 16B-aligned, ldmatrix conflict-free
#define ASTR  136
// ---- float-index smem layout (26884 floats = 107536 B -> 2 CTAs/SM) ----
#define AHI_F 0        // A_hi 96 x 136 halves (6528 f)
#define ALO_F 6528
#define SH_F  13056    // Y2/H2 fp32 81 x 130 (10530 f, +2 pad)
#define SH_STR 130
#define SW1_F 23588    // W1 10x128 (1280)
#define SX_F  24868    // x 81x10 (816)
#define SZ_F  25684    // A_hat@x 81x10 (816)
#define SP_F  26500    // pooled (128)
#define SB_F  26628    // b1|b2 (256)
#define SM_FLOATS 26884
// phase-1 agg scratch + pool scratch overlap the (temporally dead) A region
#define TRIP_F 0
#define SUM_F  6912

// ---- prepacked W2 (bf16 hi/lo) in device-global, B-fragment quad order ----
// layout: [n][g][q][4] halves, quad q holds k = 16g + {2q, 2q+1, 2q+8, 2q+9}
__device__ __align__(16) uint16_t gBhi[128 * 128];
__device__ __align__(16) uint16_t gBlo[128 * 128];

__global__ void prep_w2_kernel(const float* __restrict__ W2) {
    int idx = blockIdx.x * blockDim.x + threadIdx.x;   // 4096 quads
    if (idx >= 4096) return;
    int n = idx >> 5, g = (idx >> 2) & 7, q = idx & 3;
    int kb = 16 * g + 2 * q;
    int ks[4] = { kb, kb + 1, kb + 8, kb + 9 };
    uint16_t h[4], l[4];
    #pragma unroll
    for (int e = 0; e < 4; e++) {
        float w = W2[ks[e] * 128 + n];
        __nv_bfloat16 hb = __float2bfloat16(w);
        float fh = __bfloat162float(hb);
        __nv_bfloat16 lb = __float2bfloat16(w - fh);
        h[e] = __bfloat16_as_ushort(hb);
        l[e] = __bfloat16_as_ushort(lb);
    }
    int off = n * 128 + g * 16 + q * 4;
    uint64_t hv, lv;
    memcpy(&hv, h, 8);
    memcpy(&lv, l, 8);
    *(uint64_t*)(gBhi + off) = hv;
    *(uint64_t*)(gBlo + off) = lv;
}

// ================= constexpr index tables ===================================
struct U54 { unsigned v[54]; };
struct U27 { unsigned v[27]; };
struct U81 { unsigned v[81]; };

static constexpr U54 mkA() {
    U54 r{};
    for (int t = 0; t < 54; t++) {
        int c0 = 0, c1 = 0, c2 = 0;
        if (t < 27) { int i = t / 3, bj = t % 3, base = i * 9 + bj * 3;
                      c0 = base; c1 = base + 1; c2 = base + 2; }
        else        { int u = t - 27, j = u / 3, bi = u % 3, base = bi * 27 + j;
                      c0 = base; c1 = base + 9; c2 = base + 18; }
        r.v[t] = (unsigned)(c0 | (c1 << 8) | (c2 << 16));
    }
    return r;
}
static constexpr U27 mkB() {
    U27 r{};
    for (int s = 0; s < 27; s++) {
        int t0 = 0, t1 = 0, t2 = 0;
        if (s < 9)       { t0 = 3 * s; t1 = t0 + 1; t2 = t0 + 2; }
        else if (s < 18) { int j = s - 9; t0 = 27 + 3 * j; t1 = t0 + 1; t2 = t0 + 2; }
        else             { int bb = s - 18, bi = bb / 3, bj = bb % 3;
                           t0 = (3 * bi + 0) * 3 + bj; t1 = (3 * bi + 1) * 3 + bj;
                           t2 = (3 * bi + 2) * 3 + bj; }
        r.v[s] = (unsigned)(t0 | (t1 << 8) | (t2 << 16));
    }
    return r;
}
static constexpr U81 mkC() {
    U81 r{};
    for (int cell = 0; cell < 81; cell++) {
        int i = cell / 9, j = cell % 9, bi = i / 3, bj = j / 3;
        int b  = bi * 3 + bj;
        int ti = i * 3 + bj;
        int tj = j * 3 + bi;
        r.v[cell] = (unsigned)(i | (j << 4) | (b << 8) | (ti << 12) | (tj << 20));
    }
    return r;
}
__constant__ U54 cTabA = mkA();
__constant__ U27 cTabB = mkB();
__constant__ U81 cTabC = mkC();

// ================= PTX helpers ==============================================
__device__ __forceinline__ uint32_t smem_to_u32(const void* p) {
    uint32_t a;
    asm("{ .reg .u64 t; cvta.to.shared.u64 t, %1; cvt.u32.u64 %0, t; }"
        : "=r"(a) : "l"(p));
    return a;
}
__device__ __forceinline__ uint32_t cvt2bf16(float v0, float v1) {
    uint32_t r;
    asm("cvt.rn.bf16x2.f32 %0, %1, %2;" : "=r"(r) : "f"(v1), "f"(v0));
    return r;
}
__device__ __forceinline__ void ldsm4(uint32_t& r0, uint32_t& r1,
                                      uint32_t& r2, uint32_t& r3, uint32_t addr) {
    asm volatile("ldmatrix.sync.aligned.m8n8.x4.shared.b16 {%0,%1,%2,%3}, [%4];"
                 : "=r"(r0), "=r"(r1), "=r"(r2), "=r"(r3) : "r"(addr));
}
__device__ __forceinline__ void mma16816(float* c, uint32_t a0, uint32_t a1,
                                         uint32_t a2, uint32_t a3,
                                         uint32_t b0, uint32_t b1) {
    asm volatile(
        "mma.sync.aligned.m16n8k16.row.col.f32.bf16.bf16.f32 "
        "{%0,%1,%2,%3}, {%4,%5,%6,%7}, {%8,%9}, {%0,%1,%2,%3};"
        : "+f"(c[0]), "+f"(c[1]), "+f"(c[2]), "+f"(c[3])
        : "r"(a0), "r"(a1), "r"(a2), "r"(a3), "r"(b0), "r"(b1));
}

// ========== full 128-ch aggregation + bias + relu on 81x130 buffer ==========
__device__ __forceinline__ void agg_relu130(float* __restrict__ buf,
                                            const float* __restrict__ biasSm,
                                            float* __restrict__ sTripF,
                                            float* __restrict__ sSumF,
                                            int tid)
{
    float2* T2 = (float2*)sTripF;
    float2* S2 = (float2*)sSumF;
    const float2* B2 = (const float2*)biasSm;

    __syncthreads();

    for (int it = tid; it < 54 * 64; it += TPB) {
        int t = it >> 6, cp = it & 63;
        unsigned pk = cTabA.v[t];
        float2 a = ((const float2*)(buf + (pk & 255)         * SH_STR))[cp];
        float2 b = ((const float2*)(buf + ((pk >> 8) & 255)  * SH_STR))[cp];
        float2 c = ((const float2*)(buf + ((pk >> 16) & 255) * SH_STR))[cp];
        T2[it] = make_float2(a.x + b.x + c.x, a.y + b.y + c.y);
    }
    __syncthreads();

    for (int it = tid; it < 27 * 64; it += TPB) {
        int s = it >> 6, cp = it & 63;
        unsigned pk = cTabB.v[s];
        float2 a = T2[(pk & 255) * 64 + cp];
        float2 b = T2[((pk >> 8) & 255) * 64 + cp];
        float2 c = T2[((pk >> 16) & 255) * 64 + cp];
        S2[it] = make_float2(a.x + b.x + c.x, a.y + b.y + c.y);
    }
    __syncthreads();

    for (int it = tid; it < NCELL * 64; it += TPB) {
        int cell = it >> 6, cp = it & 63;
        unsigned pk = cTabC.v[cell];
        int i  = pk & 15, j = (pk >> 4) & 15, b = (pk >> 8) & 15;
        int ti = (pk >> 12) & 31, tj = (pk >> 20) & 31;
        float2 sR  = S2[i * 64 + cp];
        float2 sC  = S2[(9 + j) * 64 + cp];
        float2 sBx = S2[(18 + b) * 64 + cp];
        float2 tR  = T2[ti * 64 + cp];
        float2 tC  = T2[(27 + tj) * 64 + cp];
        float2 bia = B2[cp];
        float vx = (sR.x + sC.x + sBx.x - tR.x - tC.x) * (1.0f / 21.0f) + bia.x;
        float vy = (sR.y + sC.y + sBx.y - tR.y - tC.y) * (1.0f / 21.0f) + bia.y;
        ((float2*)(buf + cell * SH_STR))[cp] =
            make_float2(vx > 0.0f ? vx : 0.0f, vy > 0.0f ? vy : 0.0f);
    }
    __syncthreads();
}

// ================= main kernel ==============================================
__global__ __launch_bounds__(TPB, 2)
void sudoku_gnn_kernel(const float* __restrict__ x,
                       const float* __restrict__ W1, const float* __restrict__ b1,
                       const float* __restrict__ b2,
                       const float* __restrict__ Wa, const float* __restrict__ ba,
                       const float* __restrict__ Wc, const float* __restrict__ bc,
                       const float* __restrict__ Wn, const float* __restrict__ bn,
                       const float* __restrict__ Wt, const float* __restrict__ bt,
                       float* __restrict__ out)
{
    extern __shared__ float sm[];
    char*  smb = (char*)sm;
    float* sH  = sm + SH_F;
    float* sW1 = sm + SW1_F;
    float* sX  = sm + SX_F;
    float* sZ  = sm + SZ_F;
    float* sP  = sm + SP_F;
    float* sB  = sm + SB_F;
    float* sTripF = sm + TRIP_F;
    float* sSumF  = sm + SUM_F;

    const int tid  = threadIdx.x;
    const int wid  = tid >> 5;
    const int lane = tid & 31;
    const int g    = blockIdx.x;
    const uint32_t smu = smem_to_u32(sm);

    // ---- stage: W1 (grid-stride! 320 float4), x, biases ----
    for (int i = tid; i < 320; i += TPB)
        ((float4*)sW1)[i] = ((const float4*)W1)[i];
    {
        const float* xg = x + (size_t)g * (NCELL * 10);
        for (int i = tid; i < NCELL * 10; i += TPB) sX[i] = xg[i];
    }
    if (tid < 128) { sB[tid] = b1[tid]; sB[128 + tid] = b2[tid]; }
    __syncthreads();

    // ---- Phase 1: Zx = (A_hat @ X) on 10 raw channels (scratch in A region)
    for (int it = tid; it < 54 * 10; it += TPB) {
        int t = it / 10, f = it - t * 10;
        unsigned pk = cTabA.v[t];
        sTripF[it] = sX[(pk & 255) * 10 + f] + sX[((pk >> 8) & 255) * 10 + f]
                   + sX[((pk >> 16) & 255) * 10 + f];
    }
    __syncthreads();
    for (int it = tid; it < 27 * 10; it += TPB) {
        int s = it / 10, f = it - s * 10;
        unsigned pk = cTabB.v[s];
        sSumF[it] = sTripF[(pk & 255) * 10 + f] + sTripF[((pk >> 8) & 255) * 10 + f]
                  + sTripF[((pk >> 16) & 255) * 10 + f];
    }
    __syncthreads();
    for (int it = tid; it < NCELL * 10; it += TPB) {
        int cell = it / 10, f = it - cell * 10;
        unsigned pk = cTabC.v[cell];
        int i  = pk & 15, j = (pk >> 4) & 15, b = (pk >> 8) & 15;
        int ti = (pk >> 12) & 31, tj = (pk >> 20) & 31;
        float agg = sSumF[i * 10 + f] + sSumF[(9 + j) * 10 + f]
                  + sSumF[(18 + b) * 10 + f]
                  - sTripF[ti * 10 + f] - sTripF[(27 + tj) * 10 + f];
        sZ[it] = agg * (1.0f / 21.0f);
    }
    __syncthreads();

    // ---- Phase 2: H1 = relu(Zx@W1 + b1) -> bf16 hi/lo into A tiles;
    //      rows 81..95 zero-padded ----
    for (int it = tid; it < 96 * 64; it += TPB) {
        int cell = it >> 6, kp = it & 63;
        int k = kp << 1;
        uint32_t h = 0u, l = 0u;
        if (cell < NCELL) {
            const float* z = sZ + cell * 10;
            float v0 = sB[k], v1 = sB[k + 1];
            #pragma unroll
            for (int f = 0; f < 10; f++) {
                float zf = z[f];
                float2 wv = *(const float2*)(sW1 + f * 128 + k);
                v0 = fmaf(zf, wv.x, v0);
                v1 = fmaf(zf, wv.y, v1);
            }
            v0 = v0 > 0.0f ? v0 : 0.0f;
            v1 = v1 > 0.0f ? v1 : 0.0f;
            h = cvt2bf16(v0, v1);
            float f0 = __uint_as_float(h << 16);
            float f1 = __uint_as_float(h & 0xFFFF0000u);
            l = cvt2bf16(v0 - f0, v1 - f1);
        }
        uint32_t off = (uint32_t)cell * (ASTR * 2) + (uint32_t)k * 2;
        *(uint32_t*)(smb + AHI_F * 4 + off) = h;
        *(uint32_t*)(smb + ALO_F * 4 + off) = l;
    }
    __syncthreads();

    // ---- Phase 3: Y2 = H1 @ W2 via mma.sync bf16, 3-term compensated ----
    // 8 warps: warp = (4 n-tiles) x (3 m-tiles). B fragments come straight
    // from prepacked global bf16 (one LDG.64 per fragment, L2-resident).
    {
        const int ntb  = (wid & 3) * 4;          // 4 n-tiles (8 ch each)
        const int mtb  = (wid >> 2) * 3;         // 3 m-tiles (16 rows each)
        const int arow = lane & 15;
        const int akoff = (lane & 16) ? 8 : 0;
        const int q4   = (lane & 3) * 4;         // quad offset within k-group
        const int nrow = lane >> 2;

        float acc[3][4][4];
        #pragma unroll
        for (int mt = 0; mt < 3; mt++)
            #pragma unroll
            for (int nt = 0; nt < 4; nt++)
                #pragma unroll
                for (int qq = 0; qq < 4; qq++) acc[mt][nt][qq] = 0.0f;

        const uint32_t aHi = smu + AHI_F * 4;
        const uint32_t aLo = smu + ALO_F * 4;
        const uint16_t* bhB = gBhi + q4;
        const uint16_t* blB = gBlo + q4;

        #pragma unroll
        for (int ks = 0; ks < 8; ks++) {
            const int k0 = ks << 4;
            // B fragments: 4 n-tiles, hi+lo, single LDG.64 each
            uint2 bh[4], bl[4];
            #pragma unroll
            for (int nt = 0; nt < 4; nt++) {
                int n = (ntb + nt) * 8 + nrow;
                bh[nt] = *(const uint2*)(bhB + n * 128 + k0);
                bl[nt] = *(const uint2*)(blB + n * 128 + k0);
            }
            #pragma unroll
            for (int mt = 0; mt < 3; mt++) {
                uint32_t aOff = (uint32_t)((mtb + mt) * 16 + arow) * (ASTR * 2)
                              + (uint32_t)(k0 + akoff) * 2;
                uint32_t ah0, ah1, ah2, ah3, al0, al1, al2, al3;
                ldsm4(ah0, ah1, ah2, ah3, aHi + aOff);
                ldsm4(al0, al1, al2, al3, aLo + aOff);
                #pragma unroll
                for (int nt = 0; nt < 4; nt++) {
                    mma16816(acc[mt][nt], ah0, ah1, ah2, ah3, bh[nt].x, bh[nt].y);
                    mma16816(acc[mt][nt], ah0, ah1, ah2, ah3, bl[nt].x, bl[nt].y);
                    mma16816(acc[mt][nt], al0, al1, al2, al3, bh[nt].x, bh[nt].y);
                }
            }
        }
        // epilogue: scatter D fragments into sH (81 rows, stride 130)
        const int rbase = lane >> 2;
        const int colq  = (lane & 3) << 1;
        #pragma unroll
        for (int mt = 0; mt < 3; mt++) {
            int row = (mtb + mt) * 16 + rbase;
            #pragma unroll
            for (int nt = 0; nt < 4; nt++) {
                int col = (ntb + nt) * 8 + colq;
                if (row < NCELL)
                    *(float2*)(sH + row * SH_STR + col) =
                        make_float2(acc[mt][nt][0], acc[mt][nt][1]);
                if (row + 8 < NCELL)
                    *(float2*)(sH + (row + 8) * SH_STR + col) =
                        make_float2(acc[mt][nt][2], acc[mt][nt][3]);
            }
        }
    }

    // ---- Phase 4: H2 = relu(agg(Y2)/21 + b2) in place ----
    agg_relu130(sH, sB + 128, sTripF, sSumF, tid);

    // ---- Phase 5: mean pool (2-way split, scratch in A region) ----
    {
        int c = tid & 127, grp = tid >> 7;      // 0..1
        int cStart = grp ? 41 : 0;
        int cEnd   = grp ? NCELL : 41;
        float acc = 0.0f;
        for (int cell = cStart; cell < cEnd; cell++) acc += sH[cell * SH_STR + c];
        sTripF[grp * 128 + c] = acc;
    }
    __syncthreads();
    if (tid < 128) {
        sP[tid] = (sTripF[tid] + sTripF[128 + tid]) * (1.0f / 81.0f);
    }
    __syncthreads();

    // ---- Phase 6: heads ----
    if (tid < 104) {
        const float* W; const float* bb; int nc, col; size_t off;
        if (tid < 4)       { W = Wa; bb = ba; nc = 4;  col = tid;      off = (size_t)g * 4 + col; }
        else if (tid < 85) { W = Wc; bb = bc; nc = 81; col = tid - 4;  off = 8192u   + (size_t)g * 81 + col; }
        else if (tid < 94) { W = Wn; bb = bn; nc = 9;  col = tid - 85; off = 174080u + (size_t)g * 9  + col; }
        else               { W = Wt; bb = bt; nc = 10; col = tid - 94; off = 192512u + (size_t)g * 10 + col; }
        float acc = bb[col];
        #pragma unroll 8
        for (int k = 0; k < 128; k++)
            acc = fmaf(sP[k], W[k * nc + col], acc);
        out[off] = acc;
    }
}

extern "C" void kernel_launch(void* const* d_in, const int* in_sizes, int n_in,
                              void* d_out, int out_size)
{
    const float* x  = (const float*)d_in[0];
    const float* W1 = (const float*)d_in[3];
    const float* b1 = (const float*)d_in[4];
    const float* W2 = (const float*)d_in[5];
    const float* b2 = (const float*)d_in[6];
    const float* Wa = (const float*)d_in[7];
    const float* ba = (const float*)d_in[8];
    const float* Wc = (const float*)d_in[9];
    const float* bc = (const float*)d_in[10];
    const float* Wn = (const float*)d_in[11];
    const float* bn = (const float*)d_in[12];
    const float* Wt = (const float*)d_in[13];
    const float* bt = (const float*)d_in[14];
    float* out = (float*)d_out;

    const int nGraphs = in_sizes[0] / (NCELL * 10);   // 2048
    const size_t smemBytes = (size_t)SM_FLOATS * sizeof(float);  // ~105 KB

    // 1) prepack W2 -> bf16 hi/lo fragment-ordered global buffers
    prep_w2_kernel<<<16, 256>>>(W2);

    // 2) main fused kernel (2 CTAs/SM)
    cudaFuncSetAttribute(sudoku_gnn_kernel,
                         cudaFuncAttributeMaxDynamicSharedMemorySize,
                         (int)smemBytes);
    sudoku_gnn_kernel<<<nGraphs, TPB, smemBytes>>>(
        x, W1, b1, b2, Wa, ba, Wc, bc, Wn, bn, Wt, bt, out);
}

// round 11
// speedup vs baseline: 2.2686x; 1.1748x over previous
#include <cuda_runtime.h>
#include <cuda_bf16.h>
#include <stdint.h>

#define NCELL 81
#define TPB   256

// bf16 A tiles: row stride 136 halves (272 B), 16B-aligned, ldmatrix conflict-free
#define ASTR  136
// ---- float-index smem layout (26884 floats = 107536 B -> 2 CTAs/SM) ----
#define AHI_F 0        // A_hi 96 x 136 halves (6528 f)
#define ALO_F 6528
#define SH_F  13056    // Y2 fp32 81 x 130 (10530 f, +2 pad)
#define SH_STR 130
#define SW1_F 23588    // W1 10x128 (1280)
#define SX_F  24868    // x 81x10 (816)
#define SZ_F  25684    // A_hat@x 81x10 (816)
#define SP_F  26500    // pooled (128)
#define SB_F  26628    // b1|b2 (256)
#define SM_FLOATS 26884
// scratch overlapping the (temporally dead) A region:
#define TRIP_F  0      // 54*128 = 6912 f
#define SUM_F   6912   // 27*128 = 3456 f  (ends 10368)
#define POOLP_F 10368  // pool partials 4 x 128 = 512 f
#define HEADP_F 10880  // head partials 208 f

// ---- prepacked W2 (bf16 hi/lo) in device-global, B-fragment quad order ----
// layout: [n][g][q][4] halves, quad q holds k = 16g + {2q, 2q+1, 2q+8, 2q+9}
__device__ __align__(16) uint16_t gBhi[128 * 128];
__device__ __align__(16) uint16_t gBlo[128 * 128];

__global__ void prep_w2_kernel(const float* __restrict__ W2) {
    int idx = blockIdx.x * blockDim.x + threadIdx.x;   // 4096 quads
    if (idx >= 4096) return;
    int n = idx >> 5, g = (idx >> 2) & 7, q = idx & 3;
    int kb = 16 * g + 2 * q;
    int ks[4] = { kb, kb + 1, kb + 8, kb + 9 };
    uint16_t h[4], l[4];
    #pragma unroll
    for (int e = 0; e < 4; e++) {
        float w = W2[ks[e] * 128 + n];
        __nv_bfloat16 hb = __float2bfloat16(w);
        float fh = __bfloat162float(hb);
        __nv_bfloat16 lb = __float2bfloat16(w - fh);
        h[e] = __bfloat16_as_ushort(hb);
        l[e] = __bfloat16_as_ushort(lb);
    }
    int off = n * 128 + g * 16 + q * 4;
    uint64_t hv, lv;
    memcpy(&hv, h, 8);
    memcpy(&lv, l, 8);
    *(uint64_t*)(gBhi + off) = hv;
    *(uint64_t*)(gBlo + off) = lv;
}

// ================= constexpr index tables ===================================
struct U54 { unsigned v[54]; };
struct U27 { unsigned v[27]; };
struct U81 { unsigned v[81]; };

static constexpr U54 mkA() {
    U54 r{};
    for (int t = 0; t < 54; t++) {
        int c0 = 0, c1 = 0, c2 = 0;
        if (t < 27) { int i = t / 3, bj = t % 3, base = i * 9 + bj * 3;
                      c0 = base; c1 = base + 1; c2 = base + 2; }
        else        { int u = t - 27, j = u / 3, bi = u % 3, base = bi * 27 + j;
                      c0 = base; c1 = base + 9; c2 = base + 18; }
        r.v[t] = (unsigned)(c0 | (c1 << 8) | (c2 << 16));
    }
    return r;
}
static constexpr U27 mkB() {
    U27 r{};
    for (int s = 0; s < 27; s++) {
        int t0 = 0, t1 = 0, t2 = 0;
        if (s < 9)       { t0 = 3 * s; t1 = t0 + 1; t2 = t0 + 2; }
        else if (s < 18) { int j = s - 9; t0 = 27 + 3 * j; t1 = t0 + 1; t2 = t0 + 2; }
        else             { int bb = s - 18, bi = bb / 3, bj = bb % 3;
                           t0 = (3 * bi + 0) * 3 + bj; t1 = (3 * bi + 1) * 3 + bj;
                           t2 = (3 * bi + 2) * 3 + bj; }
        r.v[s] = (unsigned)(t0 | (t1 << 8) | (t2 << 16));
    }
    return r;
}
static constexpr U81 mkC() {
    U81 r{};
    for (int cell = 0; cell < 81; cell++) {
        int i = cell / 9, j = cell % 9, bi = i / 3, bj = j / 3;
        int b  = bi * 3 + bj;
        int ti = i * 3 + bj;
        int tj = j * 3 + bi;
        r.v[cell] = (unsigned)(i | (j << 4) | (b << 8) | (ti << 12) | (tj << 20));
    }
    return r;
}
__constant__ U54 cTabA = mkA();
__constant__ U27 cTabB = mkB();
__constant__ U81 cTabC = mkC();

// ================= PTX helpers ==============================================
__device__ __forceinline__ uint32_t smem_to_u32(const void* p) {
    uint32_t a;
    asm("{ .reg .u64 t; cvta.to.shared.u64 t, %1; cvt.u32.u64 %0, t; }"
        : "=r"(a) : "l"(p));
    return a;
}
__device__ __forceinline__ uint32_t cvt2bf16(float v0, float v1) {
    uint32_t r;
    asm("cvt.rn.bf16x2.f32 %0, %1, %2;" : "=r"(r) : "f"(v1), "f"(v0));
    return r;
}
__device__ __forceinline__ void ldsm4(uint32_t& r0, uint32_t& r1,
                                      uint32_t& r2, uint32_t& r3, uint32_t addr) {
    asm volatile("ldmatrix.sync.aligned.m8n8.x4.shared.b16 {%0,%1,%2,%3}, [%4];"
                 : "=r"(r0), "=r"(r1), "=r"(r2), "=r"(r3) : "r"(addr));
}
__device__ __forceinline__ void mma16816(float* c, uint32_t a0, uint32_t a1,
                                         uint32_t a2, uint32_t a3,
                                         uint32_t b0, uint32_t b1) {
    asm volatile(
        "mma.sync.aligned.m16n8k16.row.col.f32.bf16.bf16.f32 "
        "{%0,%1,%2,%3}, {%4,%5,%6,%7}, {%8,%9}, {%0,%1,%2,%3};"
        : "+f"(c[0]), "+f"(c[1]), "+f"(c[2]), "+f"(c[3])
        : "r"(a0), "r"(a1), "r"(a2), "r"(a3), "r"(b0), "r"(b1));
}

// ================= main kernel ==============================================
__global__ __launch_bounds__(TPB, 2)
void sudoku_gnn_kernel(const float* __restrict__ x,
                       const float* __restrict__ W1, const float* __restrict__ b1,
                       const float* __restrict__ b2,
                       const float* __restrict__ Wa, const float* __restrict__ ba,
                       const float* __restrict__ Wc, const float* __restrict__ bc,
                       const float* __restrict__ Wn, const float* __restrict__ bn,
                       const float* __restrict__ Wt, const float* __restrict__ bt,
                       float* __restrict__ out)
{
    extern __shared__ float sm[];
    char*  smb = (char*)sm;
    float* sH  = sm + SH_F;
    float* sW1 = sm + SW1_F;
    float* sX  = sm + SX_F;
    float* sZ  = sm + SZ_F;
    float* sP  = sm + SP_F;
    float* sB  = sm + SB_F;
    float* sTripF = sm + TRIP_F;
    float* sSumF  = sm + SUM_F;
    float* sPoolP = sm + POOLP_F;
    float* sHeadP = sm + HEADP_F;

    const int tid  = threadIdx.x;
    const int wid  = tid >> 5;
    const int lane = tid & 31;
    const int g    = blockIdx.x;
    const uint32_t smu = smem_to_u32(sm);

    // ---- stage: W1 (grid-stride, 320 float4), x, biases ----
    for (int i = tid; i < 320; i += TPB)
        ((float4*)sW1)[i] = ((const float4*)W1)[i];
    {
        const float* xg = x + (size_t)g * (NCELL * 10);
        for (int i = tid; i < NCELL * 10; i += TPB) sX[i] = xg[i];
    }
    if (tid < 128) { sB[tid] = b1[tid]; sB[128 + tid] = b2[tid]; }
    __syncthreads();

    // ---- Phase 1: Zx = (A_hat @ X) on 10 raw channels (scratch in A region)
    for (int it = tid; it < 54 * 10; it += TPB) {
        int t = it / 10, f = it - t * 10;
        unsigned pk = cTabA.v[t];
        sTripF[it] = sX[(pk & 255) * 10 + f] + sX[((pk >> 8) & 255) * 10 + f]
                   + sX[((pk >> 16) & 255) * 10 + f];
    }
    __syncthreads();
    for (int it = tid; it < 27 * 10; it += TPB) {
        int s = it / 10, f = it - s * 10;
        unsigned pk = cTabB.v[s];
        sSumF[it] = sTripF[(pk & 255) * 10 + f] + sTripF[((pk >> 8) & 255) * 10 + f]
                  + sTripF[((pk >> 16) & 255) * 10 + f];
    }
    __syncthreads();
    for (int it = tid; it < NCELL * 10; it += TPB) {
        int cell = it / 10, f = it - cell * 10;
        unsigned pk = cTabC.v[cell];
        int i  = pk & 15, j = (pk >> 4) & 15, b = (pk >> 8) & 15;
        int ti = (pk >> 12) & 31, tj = (pk >> 20) & 31;
        float agg = sSumF[i * 10 + f] + sSumF[(9 + j) * 10 + f]
                  + sSumF[(18 + b) * 10 + f]
                  - sTripF[ti * 10 + f] - sTripF[(27 + tj) * 10 + f];
        sZ[it] = agg * (1.0f / 21.0f);
    }
    __syncthreads();

    // ---- Phase 2: H1 = relu(Zx@W1 + b1) -> bf16 hi/lo into A tiles.
    // Loop inversion: thread owns k-pair (W1 slice in REGISTERS), streams cells;
    // z reads are warp-broadcasts. ----
    {
        const int kp  = tid & 63;           // k-pair, k = 2*kp
        const int grp = tid >> 6;           // 0..3, ~21 cells each
        const int k   = kp << 1;
        float2 w[10];
        #pragma unroll
        for (int f = 0; f < 10; f++) w[f] = *(const float2*)(sW1 + f * 128 + k);
        const float b0 = sB[k], b1v = sB[k + 1];

        int cBeg = grp * 21;
        int cEnd = cBeg + 21; if (cEnd > NCELL) cEnd = NCELL;
        for (int cell = cBeg; cell < cEnd; cell++) {
            const float* z = sZ + cell * 10;
            float v0 = b0, v1 = b1v;
            #pragma unroll
            for (int f = 0; f < 10; f++) {
                float zf = z[f];
                v0 = fmaf(zf, w[f].x, v0);
                v1 = fmaf(zf, w[f].y, v1);
            }
            v0 = v0 > 0.0f ? v0 : 0.0f;
            v1 = v1 > 0.0f ? v1 : 0.0f;
            uint32_t h = cvt2bf16(v0, v1);
            float f0 = __uint_as_float(h << 16);
            float f1 = __uint_as_float(h & 0xFFFF0000u);
            uint32_t l = cvt2bf16(v0 - f0, v1 - f1);
            uint32_t off = (uint32_t)cell * (ASTR * 2) + (uint32_t)k * 2;
            *(uint32_t*)(smb + AHI_F * 4 + off) = h;
            *(uint32_t*)(smb + ALO_F * 4 + off) = l;
        }
    }
    // zero pad rows 81..95
    for (int it = tid; it < 15 * 64; it += TPB) {
        int cell = NCELL + (it >> 6), kp = it & 63;
        uint32_t off = (uint32_t)cell * (ASTR * 2) + (uint32_t)kp * 4;
        *(uint32_t*)(smb + AHI_F * 4 + off) = 0u;
        *(uint32_t*)(smb + ALO_F * 4 + off) = 0u;
    }
    __syncthreads();

    // ---- Phase 3: Y2 = H1 @ W2 via mma.sync bf16, 3-term compensated ----
    {
        const int ntb  = (wid & 3) * 4;          // 4 n-tiles (8 ch each)
        const int mtb  = (wid >> 2) * 3;         // 3 m-tiles (16 rows each)
        const int arow = lane & 15;
        const int akoff = (lane & 16) ? 8 : 0;
        const int q4   = (lane & 3) * 4;
        const int nrow = lane >> 2;

        float acc[3][4][4];
        #pragma unroll
        for (int mt = 0; mt < 3; mt++)
            #pragma unroll
            for (int nt = 0; nt < 4; nt++)
                #pragma unroll
                for (int qq = 0; qq < 4; qq++) acc[mt][nt][qq] = 0.0f;

        const uint32_t aHi = smu + AHI_F * 4;
        const uint32_t aLo = smu + ALO_F * 4;
        const uint16_t* bhB = gBhi + q4;
        const uint16_t* blB = gBlo + q4;

        #pragma unroll
        for (int ks = 0; ks < 8; ks++) {
            const int k0 = ks << 4;
            uint2 bh[4], bl[4];
            #pragma unroll
            for (int nt = 0; nt < 4; nt++) {
                int n = (ntb + nt) * 8 + nrow;
                bh[nt] = *(const uint2*)(bhB + n * 128 + k0);
                bl[nt] = *(const uint2*)(blB + n * 128 + k0);
            }
            #pragma unroll
            for (int mt = 0; mt < 3; mt++) {
                uint32_t aOff = (uint32_t)((mtb + mt) * 16 + arow) * (ASTR * 2)
                              + (uint32_t)(k0 + akoff) * 2;
                uint32_t ah0, ah1, ah2, ah3, al0, al1, al2, al3;
                ldsm4(ah0, ah1, ah2, ah3, aHi + aOff);
                ldsm4(al0, al1, al2, al3, aLo + aOff);
                #pragma unroll
                for (int nt = 0; nt < 4; nt++) {
                    mma16816(acc[mt][nt], ah0, ah1, ah2, ah3, bh[nt].x, bh[nt].y);
                    mma16816(acc[mt][nt], ah0, ah1, ah2, ah3, bl[nt].x, bl[nt].y);
                    mma16816(acc[mt][nt], al0, al1, al2, al3, bh[nt].x, bh[nt].y);
                }
            }
        }
        // epilogue: scatter Y2 fragments into sH (81 rows, stride 130)
        const int rbase = lane >> 2;
        const int colq  = (lane & 3) << 1;
        #pragma unroll
        for (int mt = 0; mt < 3; mt++) {
            int row = (mtb + mt) * 16 + rbase;
            #pragma unroll
            for (int nt = 0; nt < 4; nt++) {
                int col = (ntb + nt) * 8 + colq;
                if (row < NCELL)
                    *(float2*)(sH + row * SH_STR + col) =
                        make_float2(acc[mt][nt][0], acc[mt][nt][1]);
                if (row + 8 < NCELL)
                    *(float2*)(sH + (row + 8) * SH_STR + col) =
                        make_float2(acc[mt][nt][2], acc[mt][nt][3]);
            }
        }
    }
    __syncthreads();

    // ---- Phase 4: agg + bias + relu + POOL, fused. H2 never materialized. --
    {
        float2* T2 = (float2*)sTripF;
        float2* S2 = (float2*)sSumF;
        const float2* B2 = (const float2*)(sB + 128);

        // pass A: triples
        for (int it = tid; it < 54 * 64; it += TPB) {
            int t = it >> 6, cp = it & 63;
            unsigned pk = cTabA.v[t];
            float2 a = ((const float2*)(sH + (pk & 255)         * SH_STR))[cp];
            float2 b = ((const float2*)(sH + ((pk >> 8) & 255)  * SH_STR))[cp];
            float2 c = ((const float2*)(sH + ((pk >> 16) & 255) * SH_STR))[cp];
            T2[it] = make_float2(a.x + b.x + c.x, a.y + b.y + c.y);
        }
        __syncthreads();

        // pass B: unit sums
        for (int it = tid; it < 27 * 64; it += TPB) {
            int s = it >> 6, cp = it & 63;
            unsigned pk = cTabB.v[s];
            float2 a = T2[(pk & 255) * 64 + cp];
            float2 b = T2[((pk >> 8) & 255) * 64 + cp];
            float2 c = T2[((pk >> 16) & 255) * 64 + cp];
            S2[it] = make_float2(a.x + b.x + c.x, a.y + b.y + c.y);
        }
        __syncthreads();

        // pass C: union + bias + relu, accumulate pool partials in registers.
        // it = cell*64 + cp; stride 256 keeps cp fixed per thread.
        float pA = 0.0f, pB = 0.0f;
        const int cp = tid & 63;
        float2 bia = B2[cp];
        for (int it = tid; it < NCELL * 64; it += TPB) {
            int cell = it >> 6;
            unsigned pk = cTabC.v[cell];
            int i  = pk & 15, j = (pk >> 4) & 15, b = (pk >> 8) & 15;
            int ti = (pk >> 12) & 31, tj = (pk >> 20) & 31;
            float2 sR  = S2[i * 64 + cp];
            float2 sC  = S2[(9 + j) * 64 + cp];
            float2 sBx = S2[(18 + b) * 64 + cp];
            float2 tR  = T2[ti * 64 + cp];
            float2 tC  = T2[(27 + tj) * 64 + cp];
            float vx = (sR.x + sC.x + sBx.x - tR.x - tC.x) * (1.0f / 21.0f) + bia.x;
            float vy = (sR.y + sC.y + sBx.y - tR.y - tC.y) * (1.0f / 21.0f) + bia.y;
            pA += vx > 0.0f ? vx : 0.0f;
            pB += vy > 0.0f ? vy : 0.0f;
        }
        // partials: 4 stripes x 64 channel-pairs (region disjoint from T2/S2)
        const int grp = tid >> 6;
        sPoolP[grp * 128 + cp * 2]     = pA;
        sPoolP[grp * 128 + cp * 2 + 1] = pB;
    }
    __syncthreads();
    if (tid < 128) {
        sP[tid] = (sPoolP[tid] + sPoolP[128 + tid] + sPoolP[256 + tid]
                 + sPoolP[384 + tid]) * (1.0f / 81.0f);
    }
    __syncthreads();

    // ---- Phase 5: heads, k-split across 208 threads ----
    {
        int half = (tid >= 128) ? 1 : 0;
        int idx  = half ? tid - 128 : tid;
        if (idx < 104) {
            const float* W; const float* bb; int nc, col;
            if (idx < 4)       { W = Wa; bb = ba; nc = 4;  col = idx; }
            else if (idx < 85) { W = Wc; bb = bc; nc = 81; col = idx - 4; }
            else if (idx < 94) { W = Wn; bb = bn; nc = 9;  col = idx - 85; }
            else               { W = Wt; bb = bt; nc = 10; col = idx - 94; }
            float acc = half ? 0.0f : bb[col];
            int kb = half << 6;
            #pragma unroll 8
            for (int k = 0; k < 64; k++)
                acc = fmaf(sP[kb + k], W[(kb + k) * nc + col], acc);
            sHeadP[half * 104 + idx] = acc;
        }
    }
    __syncthreads();
    if (tid < 104) {
        int col; size_t off;
        if (tid < 4)       { col = tid;      off = (size_t)g * 4 + col; }
        else if (tid < 85) { col = tid - 4;  off = 8192u   + (size_t)g * 81 + col; }
        else if (tid < 94) { col = tid - 85; off = 174080u + (size_t)g * 9  + col; }
        else               { col = tid - 94; off = 192512u + (size_t)g * 10 + col; }
        out[off] = sHeadP[tid] + sHeadP[104 + tid];
    }
}

extern "C" void kernel_launch(void* const* d_in, const int* in_sizes, int n_in,
                              void* d_out, int out_size)
{
    const float* x  = (const float*)d_in[0];
    const float* W1 = (const float*)d_in[3];
    const float* b1 = (const float*)d_in[4];
    const float* W2 = (const float*)d_in[5];
    const float* b2 = (const float*)d_in[6];
    const float* Wa = (const float*)d_in[7];
    const float* ba = (const float*)d_in[8];
    const float* Wc = (const float*)d_in[9];
    const float* bc = (const float*)d_in[10];
    const float* Wn = (const float*)d_in[11];
    const float* bn = (const float*)d_in[12];
    const float* Wt = (const float*)d_in[13];
    const float* bt = (const float*)d_in[14];
    float* out = (float*)d_out;

    const int nGraphs = in_sizes[0] / (NCELL * 10);   // 2048
    const size_t smemBytes = (size_t)SM_FLOATS * sizeof(float);  // ~105 KB

    prep_w2_kernel<<<16, 256>>>(W2);

    cudaFuncSetAttribute(sudoku_gnn_kernel,
                         cudaFuncAttributeMaxDynamicSharedMemorySize,
                         (int)smemBytes);
    sudoku_gnn_kernel<<<nGraphs, TPB, smemBytes>>>(
        x, W1, b1, b2, Wa, ba, Wc, bc, Wn, bn, Wt, bt, out);
}

// round 12
// speedup vs baseline: 2.5945x; 1.1437x over previous
#include <cuda_runtime.h>
#include <cuda_bf16.h>
#include <stdint.h>

#define NCELL 81
#define TPB   256

// bf16 A tiles: row stride 136 halves (272 B), 16B-aligned, ldmatrix conflict-free
#define ASTR  136
// ---- float-index smem layout (26884 floats = 107536 B -> 2 CTAs/SM) ----
#define AHI_F 0        // A_hi 96 x 136 halves (6528 f)
#define ALO_F 6528
#define SH_F  13056    // Y2 fp32 81 x 130 (10530 f, +2 pad)
#define SH_STR 130
#define SW1_F 23588    // W1 10x128 (1280)
#define SX_F  24868    // x 81x10 (816)
#define SZ_F  25684    // A_hat@x 81x10 (816)
#define SP_F  26500    // pooled (128)
#define SB_F  26628    // b1|b2 (256)
#define SM_FLOATS 26884
// scratch overlapping the (temporally dead) A region:
// phase 1 (10-channel agg):
#define TRIP_F  0      // 540 f
#define SUM_F   640    // 270 f
// phase 4 (band-blocked agg):
#define RT_F    0      // rowtrip [band*9 + r*3 + bj][ch]  27x128 = 3456
#define RS_F    3456   // rowsum  [band*3 + r][ch]          9x128 = 1152
#define CT_F    4608   // coltrip [band*9 + j][ch]         27x128 = 3456
#define BX_F    8064   // boxsum  [band*3 + bj][ch]         9x128 = 1152
#define POOLP_F 9216   // pool partials 3 x 128 = 384
#define HEADP_F 9600   // head partials 208

// ---- prepacked W2 (bf16 hi/lo) in device-global, B-fragment quad order ----
// layout: [n][g][q][4] halves, quad q holds k = 16g + {2q, 2q+1, 2q+8, 2q+9}
__device__ __align__(16) uint16_t gBhi[128 * 128];
__device__ __align__(16) uint16_t gBlo[128 * 128];

__global__ void prep_w2_kernel(const float* __restrict__ W2) {
    int idx = blockIdx.x * blockDim.x + threadIdx.x;   // 4096 quads
    if (idx >= 4096) return;
    int n = idx >> 5, g = (idx >> 2) & 7, q = idx & 3;
    int kb = 16 * g + 2 * q;
    int ks[4] = { kb, kb + 1, kb + 8, kb + 9 };
    uint16_t h[4], l[4];
    #pragma unroll
    for (int e = 0; e < 4; e++) {
        float w = W2[ks[e] * 128 + n];
        __nv_bfloat16 hb = __float2bfloat16(w);
        float fh = __bfloat162float(hb);
        __nv_bfloat16 lb = __float2bfloat16(w - fh);
        h[e] = __bfloat16_as_ushort(hb);
        l[e] = __bfloat16_as_ushort(lb);
    }
    int off = n * 128 + g * 16 + q * 4;
    uint64_t hv, lv;
    memcpy(&hv, h, 8);
    memcpy(&lv, l, 8);
    *(uint64_t*)(gBhi + off) = hv;
    *(uint64_t*)(gBlo + off) = lv;
}

// ================= constexpr index tables (phase 1 only) ====================
struct U54 { unsigned v[54]; };
struct U27 { unsigned v[27]; };
struct U81 { unsigned v[81]; };

static constexpr U54 mkA() {
    U54 r{};
    for (int t = 0; t < 54; t++) {
        int c0 = 0, c1 = 0, c2 = 0;
        if (t < 27) { int i = t / 3, bj = t % 3, base = i * 9 + bj * 3;
                      c0 = base; c1 = base + 1; c2 = base + 2; }
        else        { int u = t - 27, j = u / 3, bi = u % 3, base = bi * 27 + j;
                      c0 = base; c1 = base + 9; c2 = base + 18; }
        r.v[t] = (unsigned)(c0 | (c1 << 8) | (c2 << 16));
    }
    return r;
}
static constexpr U27 mkB() {
    U27 r{};
    for (int s = 0; s < 27; s++) {
        int t0 = 0, t1 = 0, t2 = 0;
        if (s < 9)       { t0 = 3 * s; t1 = t0 + 1; t2 = t0 + 2; }
        else if (s < 18) { int j = s - 9; t0 = 27 + 3 * j; t1 = t0 + 1; t2 = t0 + 2; }
        else             { int bb = s - 18, bi = bb / 3, bj = bb % 3;
                           t0 = (3 * bi + 0) * 3 + bj; t1 = (3 * bi + 1) * 3 + bj;
                           t2 = (3 * bi + 2) * 3 + bj; }
        r.v[s] = (unsigned)(t0 | (t1 << 8) | (t2 << 16));
    }
    return r;
}
static constexpr U81 mkC() {
    U81 r{};
    for (int cell = 0; cell < 81; cell++) {
        int i = cell / 9, j = cell % 9, bi = i / 3, bj = j / 3;
        int b  = bi * 3 + bj;
        int ti = i * 3 + bj;
        int tj = j * 3 + bi;
        r.v[cell] = (unsigned)(i | (j << 4) | (b << 8) | (ti << 12) | (tj << 20));
    }
    return r;
}
__constant__ U54 cTabA = mkA();
__constant__ U27 cTabB = mkB();
__constant__ U81 cTabC = mkC();

// ================= PTX helpers ==============================================
__device__ __forceinline__ uint32_t smem_to_u32(const void* p) {
    uint32_t a;
    asm("{ .reg .u64 t; cvta.to.shared.u64 t, %1; cvt.u32.u64 %0, t; }"
        : "=r"(a) : "l"(p));
    return a;
}
__device__ __forceinline__ uint32_t cvt2bf16(float v0, float v1) {
    uint32_t r;
    asm("cvt.rn.bf16x2.f32 %0, %1, %2;" : "=r"(r) : "f"(v1), "f"(v0));
    return r;
}
__device__ __forceinline__ void ldsm4(uint32_t& r0, uint32_t& r1,
                                      uint32_t& r2, uint32_t& r3, uint32_t addr) {
    asm volatile("ldmatrix.sync.aligned.m8n8.x4.shared.b16 {%0,%1,%2,%3}, [%4];"
                 : "=r"(r0), "=r"(r1), "=r"(r2), "=r"(r3) : "r"(addr));
}
__device__ __forceinline__ void mma16816(float* c, uint32_t a0, uint32_t a1,
                                         uint32_t a2, uint32_t a3,
                                         uint32_t b0, uint32_t b1) {
    asm volatile(
        "mma.sync.aligned.m16n8k16.row.col.f32.bf16.bf16.f32 "
        "{%0,%1,%2,%3}, {%4,%5,%6,%7}, {%8,%9}, {%0,%1,%2,%3};"
        : "+f"(c[0]), "+f"(c[1]), "+f"(c[2]), "+f"(c[3])
        : "r"(a0), "r"(a1), "r"(a2), "r"(a3), "r"(b0), "r"(b1));
}

// ================= main kernel ==============================================
__global__ __launch_bounds__(TPB, 2)
void sudoku_gnn_kernel(const float* __restrict__ x,
                       const float* __restrict__ W1, const float* __restrict__ b1,
                       const float* __restrict__ b2,
                       const float* __restrict__ Wa, const float* __restrict__ ba,
                       const float* __restrict__ Wc, const float* __restrict__ bc,
                       const float* __restrict__ Wn, const float* __restrict__ bn,
                       const float* __restrict__ Wt, const float* __restrict__ bt,
                       float* __restrict__ out)
{
    extern __shared__ float sm[];
    char*  smb = (char*)sm;
    float* sH  = sm + SH_F;
    float* sW1 = sm + SW1_F;
    float* sX  = sm + SX_F;
    float* sZ  = sm + SZ_F;
    float* sP  = sm + SP_F;
    float* sB  = sm + SB_F;
    float* sTripF = sm + TRIP_F;
    float* sSumF  = sm + SUM_F;
    float* sPoolP = sm + POOLP_F;
    float* sHeadP = sm + HEADP_F;

    const int tid  = threadIdx.x;
    const int wid  = tid >> 5;
    const int lane = tid & 31;
    const int g    = blockIdx.x;
    const uint32_t smu = smem_to_u32(sm);

    // ---- stage: W1 (grid-stride, 320 float4), x, biases ----
    for (int i = tid; i < 320; i += TPB)
        ((float4*)sW1)[i] = ((const float4*)W1)[i];
    {
        const float* xg = x + (size_t)g * (NCELL * 10);
        for (int i = tid; i < NCELL * 10; i += TPB) sX[i] = xg[i];
    }
    if (tid < 128) { sB[tid] = b1[tid]; sB[128 + tid] = b2[tid]; }
    __syncthreads();

    // ---- Phase 1: Zx = (A_hat @ X) on 10 raw channels (scratch in A region)
    for (int it = tid; it < 54 * 10; it += TPB) {
        int t = it / 10, f = it - t * 10;
        unsigned pk = cTabA.v[t];
        sTripF[it] = sX[(pk & 255) * 10 + f] + sX[((pk >> 8) & 255) * 10 + f]
                   + sX[((pk >> 16) & 255) * 10 + f];
    }
    __syncthreads();
    for (int it = tid; it < 27 * 10; it += TPB) {
        int s = it / 10, f = it - s * 10;
        unsigned pk = cTabB.v[s];
        sSumF[it] = sTripF[(pk & 255) * 10 + f] + sTripF[((pk >> 8) & 255) * 10 + f]
                  + sTripF[((pk >> 16) & 255) * 10 + f];
    }
    __syncthreads();
    for (int it = tid; it < NCELL * 10; it += TPB) {
        int cell = it / 10, f = it - cell * 10;
        unsigned pk = cTabC.v[cell];
        int i  = pk & 15, j = (pk >> 4) & 15, b = (pk >> 8) & 15;
        int ti = (pk >> 12) & 31, tj = (pk >> 20) & 31;
        float agg = sSumF[i * 10 + f] + sSumF[(9 + j) * 10 + f]
                  + sSumF[(18 + b) * 10 + f]
                  - sTripF[ti * 10 + f] - sTripF[(27 + tj) * 10 + f];
        sZ[it] = agg * (1.0f / 21.0f);
    }
    __syncthreads();

    // ---- Phase 2: H1 = relu(Zx@W1 + b1) -> bf16 hi/lo into A tiles.
    // Thread owns a k-pair (W1 slice in registers), streams cells. ----
    {
        const int kp  = tid & 63;           // k-pair, k = 2*kp
        const int grp = tid >> 6;           // 0..3, ~21 cells each
        const int k   = kp << 1;
        float2 w[10];
        #pragma unroll
        for (int f = 0; f < 10; f++) w[f] = *(const float2*)(sW1 + f * 128 + k);
        const float b0 = sB[k], b1v = sB[k + 1];

        int cBeg = grp * 21;
        int cEnd = cBeg + 21; if (cEnd > NCELL) cEnd = NCELL;
        for (int cell = cBeg; cell < cEnd; cell++) {
            const float* z = sZ + cell * 10;
            float v0 = b0, v1 = b1v;
            #pragma unroll
            for (int f = 0; f < 10; f++) {
                float zf = z[f];
                v0 = fmaf(zf, w[f].x, v0);
                v1 = fmaf(zf, w[f].y, v1);
            }
            v0 = v0 > 0.0f ? v0 : 0.0f;
            v1 = v1 > 0.0f ? v1 : 0.0f;
            uint32_t h = cvt2bf16(v0, v1);
            float f0 = __uint_as_float(h << 16);
            float f1 = __uint_as_float(h & 0xFFFF0000u);
            uint32_t l = cvt2bf16(v0 - f0, v1 - f1);
            uint32_t off = (uint32_t)cell * (ASTR * 2) + (uint32_t)k * 2;
            *(uint32_t*)(smb + AHI_F * 4 + off) = h;
            *(uint32_t*)(smb + ALO_F * 4 + off) = l;
        }
    }
    // zero pad rows 81..95
    for (int it = tid; it < 15 * 64; it += TPB) {
        int cell = NCELL + (it >> 6), kp = it & 63;
        uint32_t off = (uint32_t)cell * (ASTR * 2) + (uint32_t)kp * 4;
        *(uint32_t*)(smb + AHI_F * 4 + off) = 0u;
        *(uint32_t*)(smb + ALO_F * 4 + off) = 0u;
    }
    __syncthreads();

    // ---- Phase 3: Y2 = H1 @ W2 via mma.sync bf16, 3-term compensated ----
    {
        const int ntb  = (wid & 3) * 4;          // 4 n-tiles (8 ch each)
        const int mtb  = (wid >> 2) * 3;         // 3 m-tiles (16 rows each)
        const int arow = lane & 15;
        const int akoff = (lane & 16) ? 8 : 0;
        const int q4   = (lane & 3) * 4;
        const int nrow = lane >> 2;

        float acc[3][4][4];
        #pragma unroll
        for (int mt = 0; mt < 3; mt++)
            #pragma unroll
            for (int nt = 0; nt < 4; nt++)
                #pragma unroll
                for (int qq = 0; qq < 4; qq++) acc[mt][nt][qq] = 0.0f;

        const uint32_t aHi = smu + AHI_F * 4;
        const uint32_t aLo = smu + ALO_F * 4;
        const uint16_t* bhB = gBhi + q4;
        const uint16_t* blB = gBlo + q4;

        #pragma unroll
        for (int ks = 0; ks < 8; ks++) {
            const int k0 = ks << 4;
            uint2 bh[4], bl[4];
            #pragma unroll
            for (int nt = 0; nt < 4; nt++) {
                int n = (ntb + nt) * 8 + nrow;
                bh[nt] = *(const uint2*)(bhB + n * 128 + k0);
                bl[nt] = *(const uint2*)(blB + n * 128 + k0);
            }
            #pragma unroll
            for (int mt = 0; mt < 3; mt++) {
                uint32_t aOff = (uint32_t)((mtb + mt) * 16 + arow) * (ASTR * 2)
                              + (uint32_t)(k0 + akoff) * 2;
                uint32_t ah0, ah1, ah2, ah3, al0, al1, al2, al3;
                ldsm4(ah0, ah1, ah2, ah3, aHi + aOff);
                ldsm4(al0, al1, al2, al3, aLo + aOff);
                #pragma unroll
                for (int nt = 0; nt < 4; nt++) {
                    mma16816(acc[mt][nt], ah0, ah1, ah2, ah3, bh[nt].x, bh[nt].y);
                    mma16816(acc[mt][nt], ah0, ah1, ah2, ah3, bl[nt].x, bl[nt].y);
                    mma16816(acc[mt][nt], al0, al1, al2, al3, bh[nt].x, bh[nt].y);
                }
            }
        }
        // epilogue: scatter Y2 fragments into sH (81 rows, stride 130)
        const int rbase = lane >> 2;
        const int colq  = (lane & 3) << 1;
        #pragma unroll
        for (int mt = 0; mt < 3; mt++) {
            int row = (mtb + mt) * 16 + rbase;
            #pragma unroll
            for (int nt = 0; nt < 4; nt++) {
                int col = (ntb + nt) * 8 + colq;
                if (row < NCELL)
                    *(float2*)(sH + row * SH_STR + col) =
                        make_float2(acc[mt][nt][0], acc[mt][nt][1]);
                if (row + 8 < NCELL)
                    *(float2*)(sH + (row + 8) * SH_STR + col) =
                        make_float2(acc[mt][nt][2], acc[mt][nt][3]);
            }
        }
    }
    __syncthreads();

    // ---- Phase 4: band-blocked agg + bias + relu + pool (fused) ----
    // Pass A': item = (ch, band). Read the band's 27 cells once; build
    // rowtrips, rowsums, coltrips, boxsums in registers; write 24 values.
    for (int it = tid; it < 384; it += TPB) {
        int ch = it & 127, band = it >> 7;
        const float* base = sH + (band * 27) * SH_STR + ch;
        float v[3][9];
        #pragma unroll
        for (int r = 0; r < 3; r++)
            #pragma unroll
            for (int j = 0; j < 9; j++)
                v[r][j] = base[(r * 9 + j) * SH_STR];
        float rt[3][3];
        #pragma unroll
        for (int r = 0; r < 3; r++) {
            float rsum = 0.0f;
            #pragma unroll
            for (int bj = 0; bj < 3; bj++) {
                float t = v[r][3 * bj] + v[r][3 * bj + 1] + v[r][3 * bj + 2];
                rt[r][bj] = t;
                sm[RT_F + (band * 9 + r * 3 + bj) * 128 + ch] = t;
                rsum += t;
            }
            sm[RS_F + (band * 3 + r) * 128 + ch] = rsum;
        }
        #pragma unroll
        for (int j = 0; j < 9; j++)
            sm[CT_F + (band * 9 + j) * 128 + ch] = v[0][j] + v[1][j] + v[2][j];
        #pragma unroll
        for (int bj = 0; bj < 3; bj++)
            sm[BX_F + (band * 3 + bj) * 128 + ch] =
                rt[0][bj] + rt[1][bj] + rt[2][bj];
    }
    __syncthreads();

    // Pass C': per (ch, band): col-sums + own coltrip cached in registers,
    // evaluate 27 cells, relu+pool into partials.
    for (int it = tid; it < 384; it += TPB) {
        int ch = it & 127, band = it >> 7;
        float bias = sB[128 + ch];
        float Cj[9], ctOwn[9];
        #pragma unroll
        for (int j = 0; j < 9; j++) {
            float c0 = sm[CT_F + j * 128 + ch];
            float c1 = sm[CT_F + (9 + j) * 128 + ch];
            float c2 = sm[CT_F + (18 + j) * 128 + ch];
            Cj[j] = c0 + c1 + c2;
            ctOwn[j] = (band == 0) ? c0 : ((band == 1) ? c1 : c2);
        }
        float bx[3];
        #pragma unroll
        for (int bj = 0; bj < 3; bj++)
            bx[bj] = sm[BX_F + (band * 3 + bj) * 128 + ch];
        float acc = 0.0f;
        #pragma unroll
        for (int r = 0; r < 3; r++) {
            float R = sm[RS_F + (band * 3 + r) * 128 + ch];
            #pragma unroll
            for (int bj = 0; bj < 3; bj++) {
                float rt = sm[RT_F + (band * 9 + r * 3 + bj) * 128 + ch];
                float common = R + bx[bj] - rt;
                #pragma unroll
                for (int jj = 0; jj < 3; jj++) {
                    int j = bj * 3 + jj;
                    float val = (common + Cj[j] - ctOwn[j]) * (1.0f / 21.0f) + bias;
                    acc += val > 0.0f ? val : 0.0f;
                }
            }
        }
        sPoolP[band * 128 + ch] = acc;
    }
    __syncthreads();
    if (tid < 128)
        sP[tid] = (sPoolP[tid] + sPoolP[128 + tid] + sPoolP[256 + tid])
                * (1.0f / 81.0f);
    __syncthreads();

    // ---- Phase 5: heads, k-split across 208 threads ----
    {
        int half = (tid >= 128) ? 1 : 0;
        int idx  = half ? tid - 128 : tid;
        if (idx < 104) {
            const float* W; const float* bb; int nc, col;
            if (idx < 4)       { W = Wa; bb = ba; nc = 4;  col = idx; }
            else if (idx < 85) { W = Wc; bb = bc; nc = 81; col = idx - 4; }
            else if (idx < 94) { W = Wn; bb = bn; nc = 9;  col = idx - 85; }
            else               { W = Wt; bb = bt; nc = 10; col = idx - 94; }
            float acc = half ? 0.0f : bb[col];
            int kb = half << 6;
            #pragma unroll 8
            for (int k = 0; k < 64; k++)
                acc = fmaf(sP[kb + k], W[(kb + k) * nc + col], acc);
            sHeadP[half * 104 + idx] = acc;
        }
    }
    __syncthreads();
    if (tid < 104) {
        int col; size_t off;
        if (tid < 4)       { col = tid;      off = (size_t)g * 4 + col; }
        else if (tid < 85) { col = tid - 4;  off = 8192u   + (size_t)g * 81 + col; }
        else if (tid < 94) { col = tid - 85; off = 174080u + (size_t)g * 9  + col; }
        else               { col = tid - 94; off = 192512u + (size_t)g * 10 + col; }
        out[off] = sHeadP[tid] + sHeadP[104 + tid];
    }
}

extern "C" void kernel_launch(void* const* d_in, const int* in_sizes, int n_in,
                              void* d_out, int out_size)
{
    const float* x  = (const float*)d_in[0];
    const float* W1 = (const float*)d_in[3];
    const float* b1 = (const float*)d_in[4];
    const float* W2 = (const float*)d_in[5];
    const float* b2 = (const float*)d_in[6];
    const float* Wa = (const float*)d_in[7];
    const float* ba = (const float*)d_in[8];
    const float* Wc = (const float*)d_in[9];
    const float* bc = (const float*)d_in[10];
    const float* Wn = (const float*)d_in[11];
    const float* bn = (const float*)d_in[12];
    const float* Wt = (const float*)d_in[13];
    const float* bt = (const float*)d_in[14];
    float* out = (float*)d_out;

    const int nGraphs = in_sizes[0] / (NCELL * 10);   // 2048
    const size_t smemBytes = (size_t)SM_FLOATS * sizeof(float);  // ~105 KB

    prep_w2_kernel<<<16, 256>>>(W2);

    cudaFuncSetAttribute(sudoku_gnn_kernel,
                         cudaFuncAttributeMaxDynamicSharedMemorySize,
                         (int)smemBytes);
    sudoku_gnn_kernel<<<nGraphs, TPB, smemBytes>>>(
        x, W1, b1, b2, Wa, ba, Wc, bc, Wn, bn, Wt, bt, out);
}